// round 14
// baseline (speedup 1.0000x reference)
#include <cuda_runtime.h>
#include <cuda_bf16.h>
#include <math.h>

#define R_   2
#define K_   3
#define N_   16384
#define V_   256
#define L_   8
#define VE_  128
#define OUT_ 64
#define IN_  256
#define HID_ 512
#define C_   5
#define CH_  (C_*HID_)

// ---------------- fp32 workspace (both relations resident) ----------------
__device__ float g_x1[(size_t)R_ * N_ * CH_];
__device__ float g_x2[(size_t)R_ * N_ * CH_];
__device__ float g_outr[(size_t)R_ * N_ * HID_];
__device__ float g_hfin[(size_t)N_ * HID_];
__device__ float g_xp[(size_t)R_ * N_ * VE_];
__device__ float g_u[R_ * VE_];
__device__ float g_Wraw[(size_t)R_ * K_ * V_ * HID_];
__device__ float g_Wex [(size_t)R_ * VE_ * HID_];
__device__ float g_Wlab[(size_t)R_ * OUT_ * HID_];

// ---------------- bf16 2-plane split workspace ([hi|lo], width 2K) ----------------
__device__ __align__(16) __nv_bfloat16 g_rawA[(size_t)R_ * K_ * N_ * (2*V_)];
__device__ __align__(16) __nv_bfloat16 g_labA[(size_t)R_ * N_ * (2*OUT_)];
__device__ __align__(16) __nv_bfloat16 g_xpA [(size_t)R_ * N_ * (2*VE_)];
__device__ __align__(16) __nv_bfloat16 g_x1A [(size_t)R_ * C_ * N_ * (2*HID_)];
__device__ __align__(16) __nv_bfloat16 g_hfA [(size_t)N_ * (2*HID_)];
__device__ __align__(16) __nv_bfloat16 g_ff1A[(size_t)N_ * (2*HID_)];
__device__ __align__(16) __nv_bfloat16 g_W2T  [(size_t)C_ * HID_ * (2*HID_)];
__device__ __align__(16) __nv_bfloat16 g_WrawT[(size_t)R_ * K_ * HID_ * (2*V_)];
__device__ __align__(16) __nv_bfloat16 g_WexT [(size_t)R_ * HID_ * (2*VE_)];
__device__ __align__(16) __nv_bfloat16 g_WlabT[(size_t)R_ * HID_ * (2*OUT_)];
__device__ __align__(16) __nv_bfloat16 g_Wf1T [(size_t)HID_ * (2*HID_)];
__device__ __align__(16) __nv_bfloat16 g_Wf2T [(size_t)OUT_ * (2*HID_)];

// ---------------- PTX helpers ----------------
__device__ __forceinline__ unsigned smem_u32(const void* p) {
    unsigned a;
    asm("{ .reg .u64 t; cvta.to.shared.u64 t, %1; cvt.u32.u64 %0, t; }" : "=r"(a) : "l"(p));
    return a;
}
__device__ __forceinline__ void cp16(unsigned dst, const void* src) {
    asm volatile("cp.async.cg.shared.global [%0], [%1], 16;" :: "r"(dst), "l"(src) : "memory");
}
__device__ __forceinline__ void ldsm4(unsigned* r, unsigned addr) {
    asm volatile("ldmatrix.sync.aligned.m8n8.x4.shared.b16 {%0,%1,%2,%3}, [%4];"
        : "=r"(r[0]), "=r"(r[1]), "=r"(r[2]), "=r"(r[3]) : "r"(addr));
}
__device__ __forceinline__ void mma16816(float* d, const unsigned* a, const unsigned* b) {
    asm volatile(
        "mma.sync.aligned.m16n8k16.row.col.f32.bf16.bf16.f32 "
        "{%0,%1,%2,%3}, {%4,%5,%6,%7}, {%8,%9}, {%0,%1,%2,%3};"
        : "+f"(d[0]), "+f"(d[1]), "+f"(d[2]), "+f"(d[3])
        : "r"(a[0]), "r"(a[1]), "r"(a[2]), "r"(a[3]), "r"(b[0]), "r"(b[1]));
}
// packed 64B-pitch smem layout with XOR swizzle: 16B chunk (row, c) ->
// row*64 + ((c ^ ((row>>1)&3))<<4). Conflict-free for STS.128 and ldsm phases.
__device__ __forceinline__ unsigned swz(int row, int c) {
    return (unsigned)((row << 6) + (((c ^ (row >> 1)) & 3) << 4) + ((c & ~3) << 4));
}

// =========================================================================
// bf16 tensor-core GEMM, fused 3-product split per k-block.
// C = Ah.Bh^T + Ah.Bl^T + Al.Bh^T  (A,B 2-plane [hi|lo] along K).
// Packed swizzled smem (64B pitch) -> 3 stages fit 2 CTAs/SM (256 thr each).
// Dual B-fragment buffers (bfh/bfl): all 12 ldsm issued up-front per ks,
// then 48 MMAs back-to-back (no WAR-induced smem stall mid-stream).
// CTA: 128 x BN; warps 4(M) x (BN/64)(N); warp tile 32x64; BK=32.
// =========================================================================
template<int BN>
__global__ void __launch_bounds__(128 * (BN > 64 ? BN / 64 : 1), 2) k_tc_gemm(
    const __nv_bfloat16* __restrict__ A, long long aZo, long long aZi, int zInner,
    const __nv_bfloat16* __restrict__ B, long long bZo, long long bZi, int Kd,
    const float* __restrict__ bias, long long biasZi,
    float* __restrict__ Co, int ldc, long long cZo, long long cZi,
    const float* __restrict__ alpha_p)
{
    constexpr int BM = 128, BK = 32;
    constexpr int NWN = (BN > 64 ? BN / 64 : 1);  // warps along N (2 for BN=128)
    constexpr int THREADS = 128 * NWN;
    constexpr int WN  = BN / NWN;                 // 64
    constexpr int NT8 = WN / 8;                   // 8
    constexpr int ABP = BM * 64;                  // one A plane, packed 64B pitch
    constexpr int BBP = BN * 64;
    constexpr int STAGE = 2 * ABP + 2 * BBP;
    constexpr int APL = BM * 4, BPL = BN * 4;     // 16B chunks per plane
    constexpr int TOT = 2 * (APL + BPL);

    extern __shared__ char smem[];
    const int tid = threadIdx.x, lane = tid & 31, wid = tid >> 5;
    const int warp_m = wid & 3, warp_n = wid >> 2;
    const int m0 = blockIdx.y * BM, n0 = blockIdx.x * BN;
    const int zo = blockIdx.z / zInner, zi = blockIdx.z % zInner;
    const int ldAB = 2 * Kd;
    const __nv_bfloat16* Az = A + (long long)zo * aZo + (long long)zi * aZi;
    const __nv_bfloat16* Bz = B + (long long)zo * bZo + (long long)zi * bZi;
    float* Cz = Co + (long long)zo * cZo + (long long)zi * cZi;
    const float* biasz = bias ? bias + (long long)zi * biasZi : nullptr;

    const unsigned sb = smem_u32(smem);
    const int nkb = Kd / BK;

    float acc[2][NT8][4];
    #pragma unroll
    for (int mt = 0; mt < 2; mt++)
        #pragma unroll
        for (int nt = 0; nt < NT8; nt++)
            #pragma unroll
            for (int j = 0; j < 4; j++) acc[mt][nt][j] = 0.f;

    auto load = [&](int kb) {
        if (kb < nkb) {
            unsigned st = sb + (unsigned)(kb % 3) * STAGE;
            int k0 = kb * BK;
            #pragma unroll
            for (int q = 0; q < TOT / THREADS; q++) {
                int ch = tid + q * THREADS;
                unsigned dst; const __nv_bfloat16* src;
                if (ch < 2 * APL) {
                    int pl = (ch >= APL) ? 1 : 0;
                    int cc = ch - pl * APL;
                    int row = cc >> 2, c = cc & 3;
                    dst = st + pl * ABP + swz(row, c);
                    src = Az + (size_t)(m0 + row) * ldAB + pl * Kd + k0 + c * 8;
                } else {
                    int ch2 = ch - 2 * APL;
                    int pl = (ch2 >= BPL) ? 1 : 0;
                    int cc = ch2 - pl * BPL;
                    int row = cc >> 2, c = cc & 3;
                    dst = st + 2 * ABP + pl * BBP + swz(row, c);
                    src = Bz + (size_t)(n0 + row) * ldAB + pl * Kd + k0 + c * 8;
                }
                cp16(dst, src);
            }
        }
        asm volatile("cp.async.commit_group;" ::: "memory");
    };

    load(0); load(1);

    for (int kb = 0; kb < nkb; kb++) {
        asm volatile("cp.async.wait_group 1;" ::: "memory");
        __syncthreads();
        load(kb + 2);                       // prefetch BEFORE compute

        unsigned st = sb + (unsigned)(kb % 3) * STAGE;
        unsigned ah = st, al = st + ABP, bh = st + 2 * ABP, bl = bh + BBP;

        #pragma unroll
        for (int ks = 0; ks < 2; ks++) {
            unsigned af0[2][4], af1[2][4], bfh[NT8 / 2][4], bfl[NT8 / 2][4];
            const int arow0 = warp_m * 32 + (lane & 15);
            const int c_a = 2 * ks + (lane >> 4);
            const unsigned aoff0 = swz(arow0, c_a);
            const unsigned aoff1 = swz(arow0 + 16, c_a);
            const int rowi = lane & 7, quad = lane >> 3;
            const int nofs = (quad >> 1) * 8;
            const int c_b = 2 * ks + (quad & 1);

            // ALL fragment loads issued up-front; MMAs then run uninterrupted
            ldsm4(af0[0], ah + aoff0);
            ldsm4(af0[1], ah + aoff1);
            ldsm4(af1[0], al + aoff0);
            ldsm4(af1[1], al + aoff1);
            #pragma unroll
            for (int j = 0; j < NT8 / 2; j++) {
                int nb = warp_n * WN + j * 16 + nofs + rowi;
                ldsm4(bfh[j], bh + swz(nb, c_b));
                ldsm4(bfl[j], bl + swz(nb, c_b));
            }
            // phase 0: Ah . Bh
            #pragma unroll
            for (int mt = 0; mt < 2; mt++)
                #pragma unroll
                for (int nt = 0; nt < NT8; nt++)
                    mma16816(acc[mt][nt], af0[mt], &bfh[nt >> 1][(nt & 1) * 2]);
            // phase 2: Al . Bh
            #pragma unroll
            for (int mt = 0; mt < 2; mt++)
                #pragma unroll
                for (int nt = 0; nt < NT8; nt++)
                    mma16816(acc[mt][nt], af1[mt], &bfh[nt >> 1][(nt & 1) * 2]);
            // phase 1: Ah . Bl
            #pragma unroll
            for (int mt = 0; mt < 2; mt++)
                #pragma unroll
                for (int nt = 0; nt < NT8; nt++)
                    mma16816(acc[mt][nt], af0[mt], &bfl[nt >> 1][(nt & 1) * 2]);
        }
    }

    // ---- epilogue ----
    float alpha = alpha_p ? __ldg(alpha_p) : 0.f;
    int g = lane >> 2, q = lane & 3;
    #pragma unroll
    for (int mt = 0; mt < 2; mt++) {
        int row = m0 + warp_m * 32 + mt * 16 + g;
        #pragma unroll
        for (int nt = 0; nt < NT8; nt++) {
            int col = n0 + warp_n * WN + nt * 8 + q * 2;
            float b0 = 0.f, b1 = 0.f;
            if (biasz) { b0 = biasz[col]; b1 = biasz[col + 1]; }
            float2 v0 = make_float2(acc[mt][nt][0] + b0, acc[mt][nt][1] + b1);
            float2 v1 = make_float2(acc[mt][nt][2] + b0, acc[mt][nt][3] + b1);
            if (alpha_p) {
                v0.x = v0.x >= 0.f ? v0.x : alpha * v0.x;
                v0.y = v0.y >= 0.f ? v0.y : alpha * v0.y;
                v1.x = v1.x >= 0.f ? v1.x : alpha * v1.x;
                v1.y = v1.y >= 0.f ? v1.y : alpha * v1.y;
            }
            *reinterpret_cast<float2*>(Cz + (size_t)row * ldc + col) = v0;
            *reinterpret_cast<float2*>(Cz + (size_t)(row + 8) * ldc + col) = v1;
        }
    }
}

// ---------------- split conversions (2-plane [hi|lo]) ----------------
__device__ __forceinline__ void split2(float x, unsigned short& h, unsigned short& l) {
    __nv_bfloat16 hb = __float2bfloat16(x);
    __nv_bfloat16 lb = __float2bfloat16(x - __bfloat162float(hb));
    h = __bfloat16_as_ushort(hb); l = __bfloat16_as_ushort(lb);
}

// A-side: fp32 [N_, ldin] -> bf16 [N_, 2K]
__global__ void __launch_bounds__(256) k_splitA(
    const float* __restrict__ in, long long inZ, int ldin, int K,
    __nv_bfloat16* __restrict__ out, long long outZ)
{
    long long z = blockIdx.z;
    in += z * inZ; out += z * outZ;
    int K4 = K / 4;
    int idx = blockIdx.x * 256 + threadIdx.x;
    if (idx >= N_ * K4) return;
    int m = idx / K4, k4 = (idx % K4) * 4;
    float4 v = *reinterpret_cast<const float4*>(in + (size_t)m * ldin + k4);
    ushort4 h, l;
    split2(v.x, h.x, l.x); split2(v.y, h.y, l.y);
    split2(v.z, h.z, l.z); split2(v.w, h.w, l.w);
    size_t b = (size_t)m * 2 * K;
    *reinterpret_cast<ushort4*>(out + b + k4) = h;
    *reinterpret_cast<ushort4*>(out + b + K + k4) = l;
}

// Fused per-row LN1 stats + LN + PReLU + split. Block per (n, r).
__global__ void __launch_bounds__(256) k_lnsplit(
    const float* __restrict__ x1,
    const float* __restrict__ g1, const float* __restrict__ be1,
    const float* __restrict__ a1p, __nv_bfloat16* __restrict__ out)
{
    int n = blockIdx.x, r = blockIdx.y, tid = threadIdx.x;
    __shared__ __align__(16) float sx[CH_];
    __shared__ float rsum[8], rsum2[8], smn, srs;
    const float* xr = x1 + ((size_t)r * N_ + n) * CH_;

    float s = 0.f, s2 = 0.f;
    for (int i = tid; i < CH_ / 4; i += 256) {
        float4 t = reinterpret_cast<const float4*>(xr)[i];
        reinterpret_cast<float4*>(sx)[i] = t;
        s  += t.x + t.y + t.z + t.w;
        s2 += t.x*t.x + t.y*t.y + t.z*t.z + t.w*t.w;
    }
    int lane = tid & 31, wid = tid >> 5;
    #pragma unroll
    for (int o = 16; o > 0; o >>= 1) {
        s  += __shfl_xor_sync(0xffffffffu, s,  o);
        s2 += __shfl_xor_sync(0xffffffffu, s2, o);
    }
    if (lane == 0) { rsum[wid] = s; rsum2[wid] = s2; }
    __syncthreads();
    if (tid == 0) {
        float ts = 0.f, ts2 = 0.f;
        #pragma unroll
        for (int w2 = 0; w2 < 8; w2++) { ts += rsum[w2]; ts2 += rsum2[w2]; }
        float m = ts / (float)CH_;
        smn = m; srs = rsqrtf(ts2 / (float)CH_ - m * m + 1e-5f);
    }
    __syncthreads();

    float mn = smn, rs = srs, a = __ldg(a1p);
    for (int i4 = tid; i4 < CH_ / 4; i4 += 256) {
        int i = i4 * 4;
        int c = i / HID_, col = i % HID_;
        float4 v = reinterpret_cast<const float4*>(sx)[i4];
        float4 g = reinterpret_cast<const float4*>(g1)[i4];
        float4 b = reinterpret_cast<const float4*>(be1)[i4];
        v.x = (v.x-mn)*rs*g.x + b.x; v.y = (v.y-mn)*rs*g.y + b.y;
        v.z = (v.z-mn)*rs*g.z + b.z; v.w = (v.w-mn)*rs*g.w + b.w;
        v.x = v.x >= 0.f ? v.x : a*v.x; v.y = v.y >= 0.f ? v.y : a*v.y;
        v.z = v.z >= 0.f ? v.z : a*v.z; v.w = v.w >= 0.f ? v.w : a*v.w;
        ushort4 h, l;
        split2(v.x, h.x, l.x); split2(v.y, h.y, l.y);
        split2(v.z, h.z, l.z); split2(v.w, h.w, l.w);
        __nv_bfloat16* op = out + ((size_t)r * C_ + c) * N_ * (2*HID_) + (size_t)n * (2*HID_);
        *reinterpret_cast<ushort4*>(op + col) = h;
        *reinterpret_cast<ushort4*>(op + HID_ + col) = l;
    }
}

// B-side: fp32 [Kd, Nn] -> bf16 [Nn, 2Kd], coalesced via 32x32 smem transpose
__global__ void __launch_bounds__(256) k_splitB(
    const float* __restrict__ in, long long inZ, int Kd, int Nn,
    __nv_bfloat16* __restrict__ out, long long outZ)
{
    __shared__ float tile[32][33];
    long long z = blockIdx.z;
    in += z * inZ; out += z * outZ;
    int k0 = blockIdx.x * 32, n0 = blockIdx.y * 32;
    int tx = threadIdx.x & 31, ty = threadIdx.x >> 5;   // 32 x 8
    #pragma unroll
    for (int j = 0; j < 32; j += 8)
        tile[ty + j][tx] = in[(size_t)(k0 + ty + j) * Nn + n0 + tx];
    __syncthreads();
    #pragma unroll
    for (int j = 0; j < 32; j += 8) {
        int n = n0 + ty + j, k = k0 + tx;
        float x = tile[tx][ty + j];
        unsigned short h, l;
        split2(x, h, l);
        size_t b = (size_t)n * 2 * Kd;
        out[b + k] = __ushort_as_bfloat16(h);
        out[b + Kd + k] = __ushort_as_bfloat16(l);
    }
}

// ---------------- plain fp32 GEMM for tiny weight fusion ----------------
__global__ void __launch_bounds__(256, 2) fuse_weights_kernel(
    const float* __restrict__ femb, const float* __restrict__ eemb,
    const float* __restrict__ lemb, const float* __restrict__ W1)
{
    constexpr int BM = 64, TM = 4, BN = 128, BK = 16, TN = 8;
    int zz = blockIdx.z, r = zz / C_, c = zz % C_;
    const float* A; int M; float* out;
    if (c < K_)      { A = femb + (size_t)(r*K_+c)*V_*IN_; M = V_;   out = g_Wraw + (size_t)(r*K_+c)*V_*HID_; }
    else if (c == 3) { A = eemb + (size_t)r*VE_*IN_;       M = VE_;  out = g_Wex  + (size_t)r*VE_*HID_; }
    else             { A = lemb + (size_t)r*OUT_*IN_;      M = OUT_; out = g_Wlab + (size_t)r*OUT_*HID_; }
    const float* B = W1 + (size_t)c * IN_ * HID_;

    __shared__ __align__(16) float As[BK][BM+4];
    __shared__ __align__(16) float Bs[BK][BN];
    int tid = threadIdx.x, tx = tid % (BN/TN), ty = tid / (BN/TN);
    int row0 = blockIdx.y * BM, col0 = blockIdx.x * BN;
    float acc[TM][TN] = {};
    for (int k0 = 0; k0 < IN_; k0 += BK) {
        for (int v = tid; v < BM*(BK/4); v += 256) {
            int rr = v / (BK/4), kq = (v % (BK/4)) * 4, gr = row0 + rr;
            float4 val = make_float4(0,0,0,0);
            if (gr < M) val = *reinterpret_cast<const float4*>(A + (size_t)gr*IN_ + k0 + kq);
            As[kq][rr] = val.x; As[kq+1][rr] = val.y; As[kq+2][rr] = val.z; As[kq+3][rr] = val.w;
        }
        for (int v = tid; v < BK*(BN/4); v += 256) {
            int rr = v / (BN/4), c4 = (v % (BN/4)) * 4;
            *reinterpret_cast<float4*>(&Bs[rr][c4]) =
                *reinterpret_cast<const float4*>(B + (size_t)(k0+rr)*HID_ + col0 + c4);
        }
        __syncthreads();
        #pragma unroll
        for (int kk = 0; kk < BK; kk++) {
            float a[TM], b[TN];
            #pragma unroll
            for (int i = 0; i < TM; i++) a[i] = As[kk][ty*TM+i];
            #pragma unroll
            for (int j = 0; j < TN; j++) b[j] = Bs[kk][tx*TN+j];
            #pragma unroll
            for (int i = 0; i < TM; i++)
                #pragma unroll
                for (int j = 0; j < TN; j++) acc[i][j] += a[i]*b[j];
        }
        __syncthreads();
    }
    #pragma unroll
    for (int i = 0; i < TM; i++) {
        int gr = row0 + ty*TM + i;
        if (gr >= M) continue;
        #pragma unroll
        for (int j = 0; j < TN; j++) out[(size_t)gr*HID_ + col0 + tx*TN + j] = acc[i][j];
    }
}

// ---------------- small SIMT kernels ----------------
__global__ void k_u(const float* __restrict__ eemb, const float* __restrict__ wx)
{
    int t = blockIdx.x * blockDim.x + threadIdx.x;
    if (t >= R_ * VE_) return;
    const float* row = eemb + (size_t)t * IN_;
    float s = 0.f;
    for (int d = 0; d < IN_; d++) s += row[d] * wx[d];
    g_u[t] = s;
}

__global__ void __launch_bounds__(256) k_extra_pool(const float* __restrict__ extra)
{
    int wg = (blockIdx.x * blockDim.x + threadIdx.x) >> 5, lane = threadIdx.x & 31;
    if (wg >= R_ * N_) return;
    int r = wg / N_;
    const float* base = extra + (size_t)wg * (L_ * VE_);
    float u[4];
    #pragma unroll
    for (int j = 0; j < 4; j++) u[j] = g_u[r * VE_ + lane + 32*j];
    float x[L_][4], s[L_];
    #pragma unroll
    for (int l = 0; l < L_; l++) {
        float p = 0.f;
        #pragma unroll
        for (int j = 0; j < 4; j++) { x[l][j] = base[l*VE_ + lane + 32*j]; p += x[l][j]*u[j]; }
        #pragma unroll
        for (int o = 16; o > 0; o >>= 1) p += __shfl_xor_sync(0xffffffffu, p, o);
        s[l] = 1.f / (1.f + expf(-p));
    }
    float mx = s[0];
    #pragma unroll
    for (int l = 1; l < L_; l++) mx = fmaxf(mx, s[l]);
    float e[L_], es = 0.f;
    #pragma unroll
    for (int l = 0; l < L_; l++) { e[l] = expf(s[l]-mx); es += e[l]; }
    float inv = 1.f / es, out[4] = {0,0,0,0};
    #pragma unroll
    for (int l = 0; l < L_; l++) {
        float w = e[l]*inv;
        #pragma unroll
        for (int j = 0; j < 4; j++) out[j] += w * x[l][j];
    }
    float* op = g_xp + (size_t)wg * VE_;
    #pragma unroll
    for (int j = 0; j < 4; j++) op[lane + 32*j] = out[j];
}

// channel attention pool with in-block LN2; block per (n, r)
__global__ void __launch_bounds__(256) k_pool_c(
    const float* __restrict__ g2, const float* __restrict__ be2,
    const float* __restrict__ a2p, const float* __restrict__ w_r)
{
    int n = blockIdx.x, r = blockIdx.y, tid = threadIdx.x;
    __shared__ __align__(16) float sx[CH_];
    __shared__ float red[C_][8], rsum[8], rsum2[8], salpha[C_], smn, srs;
    const float* xr = g_x2 + ((size_t)r * N_ + n) * CH_;
    const float* wr = w_r + r * HID_;
    float s = 0.f, s2 = 0.f;
    for (int i = tid; i < CH_/4; i += 256) {
        float4 t = reinterpret_cast<const float4*>(xr)[i];
        reinterpret_cast<float4*>(sx)[i] = t;
        s += t.x+t.y+t.z+t.w; s2 += t.x*t.x+t.y*t.y+t.z*t.z+t.w*t.w;
    }
    int lane = tid & 31, wid = tid >> 5;
    #pragma unroll
    for (int o = 16; o > 0; o >>= 1) {
        s += __shfl_xor_sync(0xffffffffu, s, o);
        s2 += __shfl_xor_sync(0xffffffffu, s2, o);
    }
    if (lane == 0) { rsum[wid] = s; rsum2[wid] = s2; }
    __syncthreads();
    if (tid == 0) {
        float ts = 0.f, ts2 = 0.f;
        #pragma unroll
        for (int w2 = 0; w2 < 8; w2++) { ts += rsum[w2]; ts2 += rsum2[w2]; }
        float m = ts/(float)CH_;
        smn = m; srs = rsqrtf(ts2/(float)CH_ - m*m + 1e-5f);
    }
    __syncthreads();
    float mn = smn, rs = srs, a = __ldg(a2p);
    for (int i = tid; i < CH_; i += 256) {
        float v = (sx[i]-mn)*rs*g2[i] + be2[i];
        sx[i] = v >= 0.f ? v : a*v;
    }
    __syncthreads();
    float p[C_] = {0,0,0,0,0};
    for (int h = tid; h < HID_; h += 256) {
        float w = wr[h];
        #pragma unroll
        for (int c = 0; c < C_; c++) p[c] += sx[c*HID_+h] * w;
    }
    #pragma unroll
    for (int c = 0; c < C_; c++)
        #pragma unroll
        for (int o = 16; o > 0; o >>= 1) p[c] += __shfl_xor_sync(0xffffffffu, p[c], o);
    if (lane == 0)
        #pragma unroll
        for (int c = 0; c < C_; c++) red[c][wid] = p[c];
    __syncthreads();
    if (tid == 0) {
        float sv[C_], mx = -1e30f;
        #pragma unroll
        for (int c = 0; c < C_; c++) {
            float t = 0.f;
            #pragma unroll
            for (int w2 = 0; w2 < 8; w2++) t += red[c][w2];
            sv[c] = 1.f / (1.f + expf(-t)); mx = fmaxf(mx, sv[c]);
        }
        float es = 0.f, e[C_];
        #pragma unroll
        for (int c = 0; c < C_; c++) { e[c] = expf(sv[c]-mx); es += e[c]; }
        #pragma unroll
        for (int c = 0; c < C_; c++) salpha[c] = e[c] / es;
    }
    __syncthreads();
    float* op = g_outr + ((size_t)r * N_ + n) * HID_;
    for (int h = tid; h < HID_; h += 256) {
        float acc = 0.f;
        #pragma unroll
        for (int c = 0; c < C_; c++) acc += salpha[c] * sx[c*HID_+h];
        op[h] = acc;
    }
}

__global__ void __launch_bounds__(256) k_pool_global(const float* __restrict__ wg)
{
    int w = (blockIdx.x * blockDim.x + threadIdx.x) >> 5, lane = threadIdx.x & 31;
    if (w >= N_) return;
    const float* pa = g_outr + (size_t)w * HID_;
    const float* pb = g_outr + (size_t)N_ * HID_ + (size_t)w * HID_;
    float a[16], b[16], sa = 0.f, sb = 0.f;
    #pragma unroll
    for (int j = 0; j < 16; j++) {
        int h = lane + 32*j;
        a[j] = pa[h]; b[j] = pb[h];
        float wv = wg[h];
        sa += a[j]*wv; sb += b[j]*wv;
    }
    #pragma unroll
    for (int o = 16; o > 0; o >>= 1) {
        sa += __shfl_xor_sync(0xffffffffu, sa, o);
        sb += __shfl_xor_sync(0xffffffffu, sb, o);
    }
    sa = 1.f/(1.f+expf(-sa)); sb = 1.f/(1.f+expf(-sb));
    float mx = fmaxf(sa, sb), ea = expf(sa-mx), eb = expf(sb-mx);
    float aa = ea/(ea+eb), ab = 1.f - aa;
    float* op = g_hfin + (size_t)w * HID_;
    #pragma unroll
    for (int j = 0; j < 16; j++) op[lane + 32*j] = aa*a[j] + ab*b[j];
}

// ---------------- input mapping ----------------
struct Ins {
    const float *raw, *extra, *label, *femb, *eemb, *lemb;
    const float *w_extra, *w_r, *w_g;
    const float *W1, *b1, *g1, *be1, *a1, *W2, *b2, *g2, *be2, *a2;
    const float *Wf1, *bf1, *af, *Wf2, *bf2;
};
static void resolve(void* const* d_in, const int* sz, Ins& I)
{
    auto F = [&](int i) { return (const float*)d_in[i]; };
    if (sz[0] == R_ * K_ * N_ * V_) {
        I.raw=F(0); I.extra=F(1); I.label=F(2); I.femb=F(3); I.eemb=F(4); I.lemb=F(5);
        I.w_extra=F(6); I.w_r=F(7); I.w_g=F(8);
        I.W1=F(9); I.b1=F(10); I.g1=F(11); I.be1=F(12); I.a1=F(13);
        I.W2=F(14); I.b2=F(15); I.g2=F(16); I.be2=F(17); I.a2=F(18);
        I.Wf1=F(19); I.bf1=F(20); I.af=F(21); I.Wf2=F(22); I.bf2=F(23);
    } else {
        I.W1=F(0); I.W2=F(1); I.Wf1=F(2); I.Wf2=F(3);
        I.a1=F(4); I.a2=F(5); I.af=F(6);
        I.b1=F(7); I.b2=F(8); I.be1=F(9); I.be2=F(10); I.bf1=F(11); I.bf2=F(12);
        I.eemb=F(13); I.extra=F(14); I.femb=F(15); I.g1=F(16); I.g2=F(17);
        I.lemb=F(18); I.label=F(19); I.raw=F(20);
        I.w_extra=F(21); I.w_g=F(22); I.w_r=F(23);
    }
}

extern "C" void kernel_launch(void* const* d_in, const int* in_sizes, int n_in,
                              void* d_out, int out_size)
{
    if (n_in < 24) return;
    Ins I; resolve(d_in, in_sizes, I);

    float *px1, *px2, *pxp, *pWraw, *pWex, *pWlab, *phf;
    __nv_bfloat16 *prawA, *plabA, *pxpA, *px1A, *phfA, *pff1A;
    __nv_bfloat16 *pW2T, *pWrawT, *pWexT, *pWlabT, *pWf1T, *pWf2T;
    cudaGetSymbolAddress((void**)&px1, g_x1);     cudaGetSymbolAddress((void**)&px2, g_x2);
    cudaGetSymbolAddress((void**)&pxp, g_xp);     cudaGetSymbolAddress((void**)&pWraw, g_Wraw);
    cudaGetSymbolAddress((void**)&pWex, g_Wex);   cudaGetSymbolAddress((void**)&pWlab, g_Wlab);
    cudaGetSymbolAddress((void**)&phf, g_hfin);
    cudaGetSymbolAddress((void**)&prawA, g_rawA); cudaGetSymbolAddress((void**)&plabA, g_labA);
    cudaGetSymbolAddress((void**)&pxpA, g_xpA);   cudaGetSymbolAddress((void**)&px1A, g_x1A);
    cudaGetSymbolAddress((void**)&phfA, g_hfA);   cudaGetSymbolAddress((void**)&pff1A, g_ff1A);
    cudaGetSymbolAddress((void**)&pW2T, g_W2T);   cudaGetSymbolAddress((void**)&pWrawT, g_WrawT);
    cudaGetSymbolAddress((void**)&pWexT, g_WexT); cudaGetSymbolAddress((void**)&pWlabT, g_WlabT);
    cudaGetSymbolAddress((void**)&pWf1T, g_Wf1T); cudaGetSymbolAddress((void**)&pWf2T, g_Wf2T);

    constexpr int SM128 = 3 * (2 * 128 * 64 + 2 * 128 * 64);   // 98304 B -> 2 CTAs/SM
    constexpr int SM64  = 3 * (2 * 128 * 64 + 2 * 64 * 64);    // 73728 B
    cudaFuncSetAttribute(k_tc_gemm<128>, cudaFuncAttributeMaxDynamicSharedMemorySize, SM128);
    cudaFuncSetAttribute(k_tc_gemm<64>,  cudaFuncAttributeMaxDynamicSharedMemorySize, SM64);

    // ---- launches ordered so #4 = raw GEMM (ncu capture position) ----
    fuse_weights_kernel<<<dim3(4, 4, 10), 256>>>(I.femb, I.eemb, I.lemb, I.W1);            // 1
    k_splitB<<<dim3(V_/32, HID_/32, 6), 256>>>(pWraw, (long long)V_*HID_, V_, HID_,
                                               pWrawT, (long long)HID_*2*V_);              // 2
    k_splitA<<<dim3(4096, 1, 6), 256>>>(I.raw, (long long)N_*V_, V_, V_,
                                        prawA, (long long)N_*2*V_);                        // 3
    // raw GEMM, z = r*3+c (zInner=3): x1 channels 0..2 for both r             — launch 4
    k_tc_gemm<128><<<dim3(HID_/128, N_/128, R_*K_), 256, SM128>>>(
        prawA, (long long)K_*N_*2*V_, (long long)N_*2*V_, K_,
        pWrawT, (long long)K_*HID_*2*V_, (long long)HID_*2*V_, V_,
        I.b1, HID_,
        px1, CH_, (long long)N_*CH_, HID_, nullptr);

    // ---- rest of prolog ----
    k_u<<<1, 256>>>(I.eemb, I.w_extra);
    k_extra_pool<<<(R_ * N_) / 8, 256>>>(I.extra);
    k_splitB<<<dim3(VE_/32, HID_/32, 2), 256>>>(pWex, (long long)VE_*HID_, VE_, HID_,
                                                pWexT, (long long)HID_*2*VE_);
    k_splitB<<<dim3(OUT_/32, HID_/32, 2), 256>>>(pWlab, (long long)OUT_*HID_, OUT_, HID_,
                                                 pWlabT, (long long)HID_*2*OUT_);
    k_splitB<<<dim3(HID_/32, HID_/32, 5), 256>>>(I.W2, (long long)HID_*HID_, HID_, HID_,
                                                 pW2T, (long long)HID_*2*HID_);
    k_splitB<<<dim3(HID_/32, HID_/32, 1), 256>>>(I.Wf1, 0, HID_, HID_, pWf1T, 0);
    k_splitB<<<dim3(HID_/32, OUT_/32, 1), 256>>>(I.Wf2, 0, HID_, OUT_, pWf2T, 0);
    k_splitA<<<dim3(1024, 1, 2), 256>>>(I.label, (long long)N_*OUT_, OUT_, OUT_,
                                        plabA, (long long)N_*2*OUT_);
    k_splitA<<<dim3(2048, 1, 2), 256>>>(pxp, (long long)N_*VE_, VE_, VE_,
                                        pxpA, (long long)N_*2*VE_);

    // ---- x1 channels 3,4 for both r (z = r, zInner = 1) ----
    k_tc_gemm<128><<<dim3(HID_/128, N_/128, R_), 256, SM128>>>(
        pxpA, (long long)N_*2*VE_, 0, 1,
        pWexT, (long long)HID_*2*VE_, 0, VE_,
        I.b1 + 3*HID_, 0,
        px1 + 3*HID_, CH_, (long long)N_*CH_, 0, nullptr);
    k_tc_gemm<128><<<dim3(HID_/128, N_/128, R_), 256, SM128>>>(
        plabA, (long long)N_*2*OUT_, 0, 1,
        pWlabT, (long long)HID_*2*OUT_, 0, OUT_,
        I.b1 + 4*HID_, 0,
        px1 + 4*HID_, CH_, (long long)N_*CH_, 0, nullptr);

    // ---- LN1+split (both r), W2 GEMM (z=10), pool (both r) ----
    k_lnsplit<<<dim3(N_, R_), 256>>>(px1, I.g1, I.be1, I.a1, px1A);
    k_tc_gemm<128><<<dim3(HID_/128, N_/128, R_*C_), 256, SM128>>>(
        px1A, (long long)C_*N_*2*HID_, (long long)N_*2*HID_, C_,
        pW2T, 0, (long long)HID_*2*HID_, HID_,
        I.b2, HID_,
        px2, CH_, (long long)N_*CH_, HID_, nullptr);
    k_pool_c<<<dim3(N_, R_), 256>>>(I.g2, I.be2, I.a2, I.w_r);

    // ---- global pool + FFN head ----
    k_pool_global<<<N_ / 8, 256>>>(I.w_g);
    k_splitA<<<dim3(8192, 1, 1), 256>>>(phf, 0, HID_, HID_, phfA, 0);
    k_tc_gemm<128><<<dim3(HID_/128, N_/128, 1), 256, SM128>>>(
        phfA, 0, 0, 1, pWf1T, 0, 0, HID_,
        I.bf1, 0,
        px2, HID_, 0, 0, I.af);                        // PReLU out, [N,512]
    k_splitA<<<dim3(8192, 1, 1), 256>>>(px2, 0, HID_, HID_, pff1A, 0);
    k_tc_gemm<64><<<dim3(1, N_/128, 1), 128, SM64>>>(
        pff1A, 0, 0, 1, pWf2T, 0, 0, HID_,
        I.bf2, 0,
        (float*)d_out, OUT_, 0, 0, nullptr);
}

// round 15
// speedup vs baseline: 1.0211x; 1.0211x over previous
#include <cuda_runtime.h>
#include <cuda_bf16.h>
#include <math.h>

#define R_   2
#define K_   3
#define N_   16384
#define V_   256
#define L_   8
#define VE_  128
#define OUT_ 64
#define IN_  256
#define HID_ 512
#define C_   5
#define CH_  (C_*HID_)

// ---------------- fp32 workspace (both relations resident) ----------------
__device__ float g_x1[(size_t)R_ * N_ * CH_];
__device__ float g_x2[(size_t)R_ * N_ * CH_];
__device__ float g_outr[(size_t)R_ * N_ * HID_];
__device__ float g_hfin[(size_t)N_ * HID_];
__device__ float g_xp[(size_t)R_ * N_ * VE_];
__device__ float g_u[R_ * VE_];
__device__ float g_Wraw[(size_t)R_ * K_ * V_ * HID_];
__device__ float g_Wex [(size_t)R_ * VE_ * HID_];
__device__ float g_Wlab[(size_t)R_ * OUT_ * HID_];

// ---------------- bf16 2-plane split workspace ([hi|lo], width 2K) ----------------
__device__ __align__(16) __nv_bfloat16 g_rawA[(size_t)R_ * K_ * N_ * (2*V_)];
__device__ __align__(16) __nv_bfloat16 g_labA[(size_t)R_ * N_ * (2*OUT_)];
__device__ __align__(16) __nv_bfloat16 g_xpA [(size_t)R_ * N_ * (2*VE_)];
__device__ __align__(16) __nv_bfloat16 g_x1A [(size_t)R_ * C_ * N_ * (2*HID_)];
__device__ __align__(16) __nv_bfloat16 g_hfA [(size_t)N_ * (2*HID_)];
__device__ __align__(16) __nv_bfloat16 g_ff1A[(size_t)N_ * (2*HID_)];
__device__ __align__(16) __nv_bfloat16 g_W2T  [(size_t)C_ * HID_ * (2*HID_)];
__device__ __align__(16) __nv_bfloat16 g_WrawT[(size_t)R_ * K_ * HID_ * (2*V_)];
__device__ __align__(16) __nv_bfloat16 g_WexT [(size_t)R_ * HID_ * (2*VE_)];
__device__ __align__(16) __nv_bfloat16 g_WlabT[(size_t)R_ * HID_ * (2*OUT_)];
__device__ __align__(16) __nv_bfloat16 g_Wf1T [(size_t)HID_ * (2*HID_)];
__device__ __align__(16) __nv_bfloat16 g_Wf2T [(size_t)OUT_ * (2*HID_)];

// ---------------- PTX helpers ----------------
__device__ __forceinline__ unsigned smem_u32(const void* p) {
    unsigned a;
    asm("{ .reg .u64 t; cvta.to.shared.u64 t, %1; cvt.u32.u64 %0, t; }" : "=r"(a) : "l"(p));
    return a;
}
__device__ __forceinline__ void cp16(unsigned dst, const void* src) {
    asm volatile("cp.async.cg.shared.global [%0], [%1], 16;" :: "r"(dst), "l"(src) : "memory");
}
__device__ __forceinline__ void ldsm4(unsigned* r, unsigned addr) {
    asm volatile("ldmatrix.sync.aligned.m8n8.x4.shared.b16 {%0,%1,%2,%3}, [%4];"
        : "=r"(r[0]), "=r"(r[1]), "=r"(r[2]), "=r"(r[3]) : "r"(addr));
}
__device__ __forceinline__ void mma16816(float* d, const unsigned* a, const unsigned* b) {
    asm volatile(
        "mma.sync.aligned.m16n8k16.row.col.f32.bf16.bf16.f32 "
        "{%0,%1,%2,%3}, {%4,%5,%6,%7}, {%8,%9}, {%0,%1,%2,%3};"
        : "+f"(d[0]), "+f"(d[1]), "+f"(d[2]), "+f"(d[3])
        : "r"(a[0]), "r"(a[1]), "r"(a[2]), "r"(a[3]), "r"(b[0]), "r"(b[1]));
}
// packed 64B-pitch smem layout with XOR swizzle: 16B chunk (row, c) ->
// row*64 + ((c ^ ((row>>1)&3))<<4). Conflict-free for STS.128 and ldsm phases.
__device__ __forceinline__ unsigned swz(int row, int c) {
    return (unsigned)((row << 6) + (((c ^ (row >> 1)) & 3) << 4) + ((c & ~3) << 4));
}

// =========================================================================
// bf16 tensor-core GEMM, fused 3-product split per k-block.
// C = Ah.Bh^T + Ah.Bl^T + Al.Bh^T  (A,B 2-plane [hi|lo] along K).
// Packed swizzled smem (64B pitch) -> 3 stages fit 2 CTAs/SM (256 thr each).
// Single bf buffer (round-13 register budget); the Bl reload is interleaved
// into the phase-2 MMA stream so its latency hides under issued MMAs.
// CTA: 128 x BN; warps 4(M) x (BN/64)(N); warp tile 32x64; BK=32.
// =========================================================================
template<int BN>
__global__ void __launch_bounds__(128 * (BN > 64 ? BN / 64 : 1), 2) k_tc_gemm(
    const __nv_bfloat16* __restrict__ A, long long aZo, long long aZi, int zInner,
    const __nv_bfloat16* __restrict__ B, long long bZo, long long bZi, int Kd,
    const float* __restrict__ bias, long long biasZi,
    float* __restrict__ Co, int ldc, long long cZo, long long cZi,
    const float* __restrict__ alpha_p)
{
    constexpr int BM = 128, BK = 32;
    constexpr int NWN = (BN > 64 ? BN / 64 : 1);  // warps along N (2 for BN=128)
    constexpr int THREADS = 128 * NWN;
    constexpr int WN  = BN / NWN;                 // 64
    constexpr int NT8 = WN / 8;                   // 8
    constexpr int ABP = BM * 64;                  // one A plane, packed 64B pitch
    constexpr int BBP = BN * 64;
    constexpr int STAGE = 2 * ABP + 2 * BBP;
    constexpr int APL = BM * 4, BPL = BN * 4;     // 16B chunks per plane
    constexpr int TOT = 2 * (APL + BPL);

    extern __shared__ char smem[];
    const int tid = threadIdx.x, lane = tid & 31, wid = tid >> 5;
    const int warp_m = wid & 3, warp_n = wid >> 2;
    const int m0 = blockIdx.y * BM, n0 = blockIdx.x * BN;
    const int zo = blockIdx.z / zInner, zi = blockIdx.z % zInner;
    const int ldAB = 2 * Kd;
    const __nv_bfloat16* Az = A + (long long)zo * aZo + (long long)zi * aZi;
    const __nv_bfloat16* Bz = B + (long long)zo * bZo + (long long)zi * bZi;
    float* Cz = Co + (long long)zo * cZo + (long long)zi * cZi;
    const float* biasz = bias ? bias + (long long)zi * biasZi : nullptr;

    const unsigned sb = smem_u32(smem);
    const int nkb = Kd / BK;

    float acc[2][NT8][4];
    #pragma unroll
    for (int mt = 0; mt < 2; mt++)
        #pragma unroll
        for (int nt = 0; nt < NT8; nt++)
            #pragma unroll
            for (int j = 0; j < 4; j++) acc[mt][nt][j] = 0.f;

    auto load = [&](int kb) {
        if (kb < nkb) {
            unsigned st = sb + (unsigned)(kb % 3) * STAGE;
            int k0 = kb * BK;
            #pragma unroll
            for (int q = 0; q < TOT / THREADS; q++) {
                int ch = tid + q * THREADS;
                unsigned dst; const __nv_bfloat16* src;
                if (ch < 2 * APL) {
                    int pl = (ch >= APL) ? 1 : 0;
                    int cc = ch - pl * APL;
                    int row = cc >> 2, c = cc & 3;
                    dst = st + pl * ABP + swz(row, c);
                    src = Az + (size_t)(m0 + row) * ldAB + pl * Kd + k0 + c * 8;
                } else {
                    int ch2 = ch - 2 * APL;
                    int pl = (ch2 >= BPL) ? 1 : 0;
                    int cc = ch2 - pl * BPL;
                    int row = cc >> 2, c = cc & 3;
                    dst = st + 2 * ABP + pl * BBP + swz(row, c);
                    src = Bz + (size_t)(n0 + row) * ldAB + pl * Kd + k0 + c * 8;
                }
                cp16(dst, src);
            }
        }
        asm volatile("cp.async.commit_group;" ::: "memory");
    };

    load(0); load(1);

    for (int kb = 0; kb < nkb; kb++) {
        asm volatile("cp.async.wait_group 1;" ::: "memory");
        __syncthreads();
        load(kb + 2);                       // prefetch BEFORE compute

        unsigned st = sb + (unsigned)(kb % 3) * STAGE;
        unsigned ah = st, al = st + ABP, bh = st + 2 * ABP, bl = bh + BBP;

        #pragma unroll
        for (int ks = 0; ks < 2; ks++) {
            unsigned af0[2][4], af1[2][4], bf[NT8 / 2][4];
            const int arow0 = warp_m * 32 + (lane & 15);
            const int c_a = 2 * ks + (lane >> 4);
            const unsigned aoff0 = swz(arow0, c_a);
            const unsigned aoff1 = swz(arow0 + 16, c_a);
            const int rowi = lane & 7, quad = lane >> 3;
            const int nofs = (quad >> 1) * 8;
            const int c_b = 2 * ks + (quad & 1);

            ldsm4(af0[0], ah + aoff0);
            ldsm4(af0[1], ah + aoff1);
            ldsm4(af1[0], al + aoff0);
            ldsm4(af1[1], al + aoff1);
            #pragma unroll
            for (int j = 0; j < NT8 / 2; j++) {
                int nb = warp_n * WN + j * 16 + nofs + rowi;
                ldsm4(bf[j], bh + swz(nb, c_b));
            }
            // phase 0: Ah . Bh
            #pragma unroll
            for (int mt = 0; mt < 2; mt++)
                #pragma unroll
                for (int nt = 0; nt < NT8; nt++)
                    mma16816(acc[mt][nt], af0[mt], &bf[nt >> 1][(nt & 1) * 2]);
            // phase 2: Al . Bh, with per-j Bl reload interleaved right after
            // the 4 MMAs that consume bf[j] (MMA reads at issue -> WAR clears)
            #pragma unroll
            for (int j = 0; j < NT8 / 2; j++) {
                #pragma unroll
                for (int mt = 0; mt < 2; mt++) {
                    mma16816(acc[mt][2 * j + 0], af1[mt], &bf[j][0]);
                    mma16816(acc[mt][2 * j + 1], af1[mt], &bf[j][2]);
                }
                int nb = warp_n * WN + j * 16 + nofs + rowi;
                ldsm4(bf[j], bl + swz(nb, c_b));
            }
            // phase 1: Ah . Bl
            #pragma unroll
            for (int mt = 0; mt < 2; mt++)
                #pragma unroll
                for (int nt = 0; nt < NT8; nt++)
                    mma16816(acc[mt][nt], af0[mt], &bf[nt >> 1][(nt & 1) * 2]);
        }
    }

    // ---- epilogue ----
    float alpha = alpha_p ? __ldg(alpha_p) : 0.f;
    int g = lane >> 2, q = lane & 3;
    #pragma unroll
    for (int mt = 0; mt < 2; mt++) {
        int row = m0 + warp_m * 32 + mt * 16 + g;
        #pragma unroll
        for (int nt = 0; nt < NT8; nt++) {
            int col = n0 + warp_n * WN + nt * 8 + q * 2;
            float b0 = 0.f, b1 = 0.f;
            if (biasz) { b0 = biasz[col]; b1 = biasz[col + 1]; }
            float2 v0 = make_float2(acc[mt][nt][0] + b0, acc[mt][nt][1] + b1);
            float2 v1 = make_float2(acc[mt][nt][2] + b0, acc[mt][nt][3] + b1);
            if (alpha_p) {
                v0.x = v0.x >= 0.f ? v0.x : alpha * v0.x;
                v0.y = v0.y >= 0.f ? v0.y : alpha * v0.y;
                v1.x = v1.x >= 0.f ? v1.x : alpha * v1.x;
                v1.y = v1.y >= 0.f ? v1.y : alpha * v1.y;
            }
            *reinterpret_cast<float2*>(Cz + (size_t)row * ldc + col) = v0;
            *reinterpret_cast<float2*>(Cz + (size_t)(row + 8) * ldc + col) = v1;
        }
    }
}

// ---------------- split conversions (2-plane [hi|lo]) ----------------
__device__ __forceinline__ void split2(float x, unsigned short& h, unsigned short& l) {
    __nv_bfloat16 hb = __float2bfloat16(x);
    __nv_bfloat16 lb = __float2bfloat16(x - __bfloat162float(hb));
    h = __bfloat16_as_ushort(hb); l = __bfloat16_as_ushort(lb);
}

// A-side: fp32 [N_, ldin] -> bf16 [N_, 2K]
__global__ void __launch_bounds__(256) k_splitA(
    const float* __restrict__ in, long long inZ, int ldin, int K,
    __nv_bfloat16* __restrict__ out, long long outZ)
{
    long long z = blockIdx.z;
    in += z * inZ; out += z * outZ;
    int K4 = K / 4;
    int idx = blockIdx.x * 256 + threadIdx.x;
    if (idx >= N_ * K4) return;
    int m = idx / K4, k4 = (idx % K4) * 4;
    float4 v = *reinterpret_cast<const float4*>(in + (size_t)m * ldin + k4);
    ushort4 h, l;
    split2(v.x, h.x, l.x); split2(v.y, h.y, l.y);
    split2(v.z, h.z, l.z); split2(v.w, h.w, l.w);
    size_t b = (size_t)m * 2 * K;
    *reinterpret_cast<ushort4*>(out + b + k4) = h;
    *reinterpret_cast<ushort4*>(out + b + K + k4) = l;
}

// Fused per-row LN1 stats + LN + PReLU + split. Block per (n, r).
__global__ void __launch_bounds__(256) k_lnsplit(
    const float* __restrict__ x1,
    const float* __restrict__ g1, const float* __restrict__ be1,
    const float* __restrict__ a1p, __nv_bfloat16* __restrict__ out)
{
    int n = blockIdx.x, r = blockIdx.y, tid = threadIdx.x;
    __shared__ __align__(16) float sx[CH_];
    __shared__ float rsum[8], rsum2[8], smn, srs;
    const float* xr = x1 + ((size_t)r * N_ + n) * CH_;

    float s = 0.f, s2 = 0.f;
    for (int i = tid; i < CH_ / 4; i += 256) {
        float4 t = reinterpret_cast<const float4*>(xr)[i];
        reinterpret_cast<float4*>(sx)[i] = t;
        s  += t.x + t.y + t.z + t.w;
        s2 += t.x*t.x + t.y*t.y + t.z*t.z + t.w*t.w;
    }
    int lane = tid & 31, wid = tid >> 5;
    #pragma unroll
    for (int o = 16; o > 0; o >>= 1) {
        s  += __shfl_xor_sync(0xffffffffu, s,  o);
        s2 += __shfl_xor_sync(0xffffffffu, s2, o);
    }
    if (lane == 0) { rsum[wid] = s; rsum2[wid] = s2; }
    __syncthreads();
    if (tid == 0) {
        float ts = 0.f, ts2 = 0.f;
        #pragma unroll
        for (int w2 = 0; w2 < 8; w2++) { ts += rsum[w2]; ts2 += rsum2[w2]; }
        float m = ts / (float)CH_;
        smn = m; srs = rsqrtf(ts2 / (float)CH_ - m * m + 1e-5f);
    }
    __syncthreads();

    float mn = smn, rs = srs, a = __ldg(a1p);
    for (int i4 = tid; i4 < CH_ / 4; i4 += 256) {
        int i = i4 * 4;
        int c = i / HID_, col = i % HID_;
        float4 v = reinterpret_cast<const float4*>(sx)[i4];
        float4 g = reinterpret_cast<const float4*>(g1)[i4];
        float4 b = reinterpret_cast<const float4*>(be1)[i4];
        v.x = (v.x-mn)*rs*g.x + b.x; v.y = (v.y-mn)*rs*g.y + b.y;
        v.z = (v.z-mn)*rs*g.z + b.z; v.w = (v.w-mn)*rs*g.w + b.w;
        v.x = v.x >= 0.f ? v.x : a*v.x; v.y = v.y >= 0.f ? v.y : a*v.y;
        v.z = v.z >= 0.f ? v.z : a*v.z; v.w = v.w >= 0.f ? v.w : a*v.w;
        ushort4 h, l;
        split2(v.x, h.x, l.x); split2(v.y, h.y, l.y);
        split2(v.z, h.z, l.z); split2(v.w, h.w, l.w);
        __nv_bfloat16* op = out + ((size_t)r * C_ + c) * N_ * (2*HID_) + (size_t)n * (2*HID_);
        *reinterpret_cast<ushort4*>(op + col) = h;
        *reinterpret_cast<ushort4*>(op + HID_ + col) = l;
    }
}

// B-side: fp32 [Kd, Nn] -> bf16 [Nn, 2Kd], coalesced via 32x32 smem transpose
__global__ void __launch_bounds__(256) k_splitB(
    const float* __restrict__ in, long long inZ, int Kd, int Nn,
    __nv_bfloat16* __restrict__ out, long long outZ)
{
    __shared__ float tile[32][33];
    long long z = blockIdx.z;
    in += z * inZ; out += z * outZ;
    int k0 = blockIdx.x * 32, n0 = blockIdx.y * 32;
    int tx = threadIdx.x & 31, ty = threadIdx.x >> 5;   // 32 x 8
    #pragma unroll
    for (int j = 0; j < 32; j += 8)
        tile[ty + j][tx] = in[(size_t)(k0 + ty + j) * Nn + n0 + tx];
    __syncthreads();
    #pragma unroll
    for (int j = 0; j < 32; j += 8) {
        int n = n0 + ty + j, k = k0 + tx;
        float x = tile[tx][ty + j];
        unsigned short h, l;
        split2(x, h, l);
        size_t b = (size_t)n * 2 * Kd;
        out[b + k] = __ushort_as_bfloat16(h);
        out[b + Kd + k] = __ushort_as_bfloat16(l);
    }
}

// ---------------- plain fp32 GEMM for tiny weight fusion ----------------
__global__ void __launch_bounds__(256, 2) fuse_weights_kernel(
    const float* __restrict__ femb, const float* __restrict__ eemb,
    const float* __restrict__ lemb, const float* __restrict__ W1)
{
    constexpr int BM = 64, TM = 4, BN = 128, BK = 16, TN = 8;
    int zz = blockIdx.z, r = zz / C_, c = zz % C_;
    const float* A; int M; float* out;
    if (c < K_)      { A = femb + (size_t)(r*K_+c)*V_*IN_; M = V_;   out = g_Wraw + (size_t)(r*K_+c)*V_*HID_; }
    else if (c == 3) { A = eemb + (size_t)r*VE_*IN_;       M = VE_;  out = g_Wex  + (size_t)r*VE_*HID_; }
    else             { A = lemb + (size_t)r*OUT_*IN_;      M = OUT_; out = g_Wlab + (size_t)r*OUT_*HID_; }
    const float* B = W1 + (size_t)c * IN_ * HID_;

    __shared__ __align__(16) float As[BK][BM+4];
    __shared__ __align__(16) float Bs[BK][BN];
    int tid = threadIdx.x, tx = tid % (BN/TN), ty = tid / (BN/TN);
    int row0 = blockIdx.y * BM, col0 = blockIdx.x * BN;
    float acc[TM][TN] = {};
    for (int k0 = 0; k0 < IN_; k0 += BK) {
        for (int v = tid; v < BM*(BK/4); v += 256) {
            int rr = v / (BK/4), kq = (v % (BK/4)) * 4, gr = row0 + rr;
            float4 val = make_float4(0,0,0,0);
            if (gr < M) val = *reinterpret_cast<const float4*>(A + (size_t)gr*IN_ + k0 + kq);
            As[kq][rr] = val.x; As[kq+1][rr] = val.y; As[kq+2][rr] = val.z; As[kq+3][rr] = val.w;
        }
        for (int v = tid; v < BK*(BN/4); v += 256) {
            int rr = v / (BN/4), c4 = (v % (BN/4)) * 4;
            *reinterpret_cast<float4*>(&Bs[rr][c4]) =
                *reinterpret_cast<const float4*>(B + (size_t)(k0+rr)*HID_ + col0 + c4);
        }
        __syncthreads();
        #pragma unroll
        for (int kk = 0; kk < BK; kk++) {
            float a[TM], b[TN];
            #pragma unroll
            for (int i = 0; i < TM; i++) a[i] = As[kk][ty*TM+i];
            #pragma unroll
            for (int j = 0; j < TN; j++) b[j] = Bs[kk][tx*TN+j];
            #pragma unroll
            for (int i = 0; i < TM; i++)
                #pragma unroll
                for (int j = 0; j < TN; j++) acc[i][j] += a[i]*b[j];
        }
        __syncthreads();
    }
    #pragma unroll
    for (int i = 0; i < TM; i++) {
        int gr = row0 + ty*TM + i;
        if (gr >= M) continue;
        #pragma unroll
        for (int j = 0; j < TN; j++) out[(size_t)gr*HID_ + col0 + tx*TN + j] = acc[i][j];
    }
}

// ---------------- small SIMT kernels ----------------
__global__ void k_u(const float* __restrict__ eemb, const float* __restrict__ wx)
{
    int t = blockIdx.x * blockDim.x + threadIdx.x;
    if (t >= R_ * VE_) return;
    const float* row = eemb + (size_t)t * IN_;
    float s = 0.f;
    for (int d = 0; d < IN_; d++) s += row[d] * wx[d];
    g_u[t] = s;
}

__global__ void __launch_bounds__(256) k_extra_pool(const float* __restrict__ extra)
{
    int wg = (blockIdx.x * blockDim.x + threadIdx.x) >> 5, lane = threadIdx.x & 31;
    if (wg >= R_ * N_) return;
    int r = wg / N_;
    const float* base = extra + (size_t)wg * (L_ * VE_);
    float u[4];
    #pragma unroll
    for (int j = 0; j < 4; j++) u[j] = g_u[r * VE_ + lane + 32*j];
    float x[L_][4], s[L_];
    #pragma unroll
    for (int l = 0; l < L_; l++) {
        float p = 0.f;
        #pragma unroll
        for (int j = 0; j < 4; j++) { x[l][j] = base[l*VE_ + lane + 32*j]; p += x[l][j]*u[j]; }
        #pragma unroll
        for (int o = 16; o > 0; o >>= 1) p += __shfl_xor_sync(0xffffffffu, p, o);
        s[l] = 1.f / (1.f + expf(-p));
    }
    float mx = s[0];
    #pragma unroll
    for (int l = 1; l < L_; l++) mx = fmaxf(mx, s[l]);
    float e[L_], es = 0.f;
    #pragma unroll
    for (int l = 0; l < L_; l++) { e[l] = expf(s[l]-mx); es += e[l]; }
    float inv = 1.f / es, out[4] = {0,0,0,0};
    #pragma unroll
    for (int l = 0; l < L_; l++) {
        float w = e[l]*inv;
        #pragma unroll
        for (int j = 0; j < 4; j++) out[j] += w * x[l][j];
    }
    float* op = g_xp + (size_t)wg * VE_;
    #pragma unroll
    for (int j = 0; j < 4; j++) op[lane + 32*j] = out[j];
}

// channel attention pool with in-block LN2; block per (n, r)
__global__ void __launch_bounds__(256) k_pool_c(
    const float* __restrict__ g2, const float* __restrict__ be2,
    const float* __restrict__ a2p, const float* __restrict__ w_r)
{
    int n = blockIdx.x, r = blockIdx.y, tid = threadIdx.x;
    __shared__ __align__(16) float sx[CH_];
    __shared__ float red[C_][8], rsum[8], rsum2[8], salpha[C_], smn, srs;
    const float* xr = g_x2 + ((size_t)r * N_ + n) * CH_;
    const float* wr = w_r + r * HID_;
    float s = 0.f, s2 = 0.f;
    for (int i = tid; i < CH_/4; i += 256) {
        float4 t = reinterpret_cast<const float4*>(xr)[i];
        reinterpret_cast<float4*>(sx)[i] = t;
        s += t.x+t.y+t.z+t.w; s2 += t.x*t.x+t.y*t.y+t.z*t.z+t.w*t.w;
    }
    int lane = tid & 31, wid = tid >> 5;
    #pragma unroll
    for (int o = 16; o > 0; o >>= 1) {
        s += __shfl_xor_sync(0xffffffffu, s, o);
        s2 += __shfl_xor_sync(0xffffffffu, s2, o);
    }
    if (lane == 0) { rsum[wid] = s; rsum2[wid] = s2; }
    __syncthreads();
    if (tid == 0) {
        float ts = 0.f, ts2 = 0.f;
        #pragma unroll
        for (int w2 = 0; w2 < 8; w2++) { ts += rsum[w2]; ts2 += rsum2[w2]; }
        float m = ts/(float)CH_;
        smn = m; srs = rsqrtf(ts2/(float)CH_ - m*m + 1e-5f);
    }
    __syncthreads();
    float mn = smn, rs = srs, a = __ldg(a2p);
    for (int i = tid; i < CH_; i += 256) {
        float v = (sx[i]-mn)*rs*g2[i] + be2[i];
        sx[i] = v >= 0.f ? v : a*v;
    }
    __syncthreads();
    float p[C_] = {0,0,0,0,0};
    for (int h = tid; h < HID_; h += 256) {
        float w = wr[h];
        #pragma unroll
        for (int c = 0; c < C_; c++) p[c] += sx[c*HID_+h] * w;
    }
    #pragma unroll
    for (int c = 0; c < C_; c++)
        #pragma unroll
        for (int o = 16; o > 0; o >>= 1) p[c] += __shfl_xor_sync(0xffffffffu, p[c], o);
    if (lane == 0)
        #pragma unroll
        for (int c = 0; c < C_; c++) red[c][wid] = p[c];
    __syncthreads();
    if (tid == 0) {
        float sv[C_], mx = -1e30f;
        #pragma unroll
        for (int c = 0; c < C_; c++) {
            float t = 0.f;
            #pragma unroll
            for (int w2 = 0; w2 < 8; w2++) t += red[c][w2];
            sv[c] = 1.f / (1.f + expf(-t)); mx = fmaxf(mx, sv[c]);
        }
        float es = 0.f, e[C_];
        #pragma unroll
        for (int c = 0; c < C_; c++) { e[c] = expf(sv[c]-mx); es += e[c]; }
        #pragma unroll
        for (int c = 0; c < C_; c++) salpha[c] = e[c] / es;
    }
    __syncthreads();
    float* op = g_outr + ((size_t)r * N_ + n) * HID_;
    for (int h = tid; h < HID_; h += 256) {
        float acc = 0.f;
        #pragma unroll
        for (int c = 0; c < C_; c++) acc += salpha[c] * sx[c*HID_+h];
        op[h] = acc;
    }
}

__global__ void __launch_bounds__(256) k_pool_global(const float* __restrict__ wg)
{
    int w = (blockIdx.x * blockDim.x + threadIdx.x) >> 5, lane = threadIdx.x & 31;
    if (w >= N_) return;
    const float* pa = g_outr + (size_t)w * HID_;
    const float* pb = g_outr + (size_t)N_ * HID_ + (size_t)w * HID_;
    float a[16], b[16], sa = 0.f, sb = 0.f;
    #pragma unroll
    for (int j = 0; j < 16; j++) {
        int h = lane + 32*j;
        a[j] = pa[h]; b[j] = pb[h];
        float wv = wg[h];
        sa += a[j]*wv; sb += b[j]*wv;
    }
    #pragma unroll
    for (int o = 16; o > 0; o >>= 1) {
        sa += __shfl_xor_sync(0xffffffffu, sa, o);
        sb += __shfl_xor_sync(0xffffffffu, sb, o);
    }
    sa = 1.f/(1.f+expf(-sa)); sb = 1.f/(1.f+expf(-sb));
    float mx = fmaxf(sa, sb), ea = expf(sa-mx), eb = expf(sb-mx);
    float aa = ea/(ea+eb), ab = 1.f - aa;
    float* op = g_hfin + (size_t)w * HID_;
    #pragma unroll
    for (int j = 0; j < 16; j++) op[lane + 32*j] = aa*a[j] + ab*b[j];
}

// ---------------- input mapping ----------------
struct Ins {
    const float *raw, *extra, *label, *femb, *eemb, *lemb;
    const float *w_extra, *w_r, *w_g;
    const float *W1, *b1, *g1, *be1, *a1, *W2, *b2, *g2, *be2, *a2;
    const float *Wf1, *bf1, *af, *Wf2, *bf2;
};
static void resolve(void* const* d_in, const int* sz, Ins& I)
{
    auto F = [&](int i) { return (const float*)d_in[i]; };
    if (sz[0] == R_ * K_ * N_ * V_) {
        I.raw=F(0); I.extra=F(1); I.label=F(2); I.femb=F(3); I.eemb=F(4); I.lemb=F(5);
        I.w_extra=F(6); I.w_r=F(7); I.w_g=F(8);
        I.W1=F(9); I.b1=F(10); I.g1=F(11); I.be1=F(12); I.a1=F(13);
        I.W2=F(14); I.b2=F(15); I.g2=F(16); I.be2=F(17); I.a2=F(18);
        I.Wf1=F(19); I.bf1=F(20); I.af=F(21); I.Wf2=F(22); I.bf2=F(23);
    } else {
        I.W1=F(0); I.W2=F(1); I.Wf1=F(2); I.Wf2=F(3);
        I.a1=F(4); I.a2=F(5); I.af=F(6);
        I.b1=F(7); I.b2=F(8); I.be1=F(9); I.be2=F(10); I.bf1=F(11); I.bf2=F(12);
        I.eemb=F(13); I.extra=F(14); I.femb=F(15); I.g1=F(16); I.g2=F(17);
        I.lemb=F(18); I.label=F(19); I.raw=F(20);
        I.w_extra=F(21); I.w_g=F(22); I.w_r=F(23);
    }
}

extern "C" void kernel_launch(void* const* d_in, const int* in_sizes, int n_in,
                              void* d_out, int out_size)
{
    if (n_in < 24) return;
    Ins I; resolve(d_in, in_sizes, I);

    float *px1, *px2, *pxp, *pWraw, *pWex, *pWlab, *phf;
    __nv_bfloat16 *prawA, *plabA, *pxpA, *px1A, *phfA, *pff1A;
    __nv_bfloat16 *pW2T, *pWrawT, *pWexT, *pWlabT, *pWf1T, *pWf2T;
    cudaGetSymbolAddress((void**)&px1, g_x1);     cudaGetSymbolAddress((void**)&px2, g_x2);
    cudaGetSymbolAddress((void**)&pxp, g_xp);     cudaGetSymbolAddress((void**)&pWraw, g_Wraw);
    cudaGetSymbolAddress((void**)&pWex, g_Wex);   cudaGetSymbolAddress((void**)&pWlab, g_Wlab);
    cudaGetSymbolAddress((void**)&phf, g_hfin);
    cudaGetSymbolAddress((void**)&prawA, g_rawA); cudaGetSymbolAddress((void**)&plabA, g_labA);
    cudaGetSymbolAddress((void**)&pxpA, g_xpA);   cudaGetSymbolAddress((void**)&px1A, g_x1A);
    cudaGetSymbolAddress((void**)&phfA, g_hfA);   cudaGetSymbolAddress((void**)&pff1A, g_ff1A);
    cudaGetSymbolAddress((void**)&pW2T, g_W2T);   cudaGetSymbolAddress((void**)&pWrawT, g_WrawT);
    cudaGetSymbolAddress((void**)&pWexT, g_WexT); cudaGetSymbolAddress((void**)&pWlabT, g_WlabT);
    cudaGetSymbolAddress((void**)&pWf1T, g_Wf1T); cudaGetSymbolAddress((void**)&pWf2T, g_Wf2T);

    constexpr int SM128 = 3 * (2 * 128 * 64 + 2 * 128 * 64);   // 98304 B -> 2 CTAs/SM
    constexpr int SM64  = 3 * (2 * 128 * 64 + 2 * 64 * 64);    // 73728 B
    cudaFuncSetAttribute(k_tc_gemm<128>, cudaFuncAttributeMaxDynamicSharedMemorySize, SM128);
    cudaFuncSetAttribute(k_tc_gemm<64>,  cudaFuncAttributeMaxDynamicSharedMemorySize, SM64);

    // ---- launches ordered so #4 = raw GEMM (ncu capture position) ----
    fuse_weights_kernel<<<dim3(4, 4, 10), 256>>>(I.femb, I.eemb, I.lemb, I.W1);            // 1
    k_splitB<<<dim3(V_/32, HID_/32, 6), 256>>>(pWraw, (long long)V_*HID_, V_, HID_,
                                               pWrawT, (long long)HID_*2*V_);              // 2
    k_splitA<<<dim3(4096, 1, 6), 256>>>(I.raw, (long long)N_*V_, V_, V_,
                                        prawA, (long long)N_*2*V_);                        // 3
    // raw GEMM, z = r*3+c (zInner=3): x1 channels 0..2 for both r             — launch 4
    k_tc_gemm<128><<<dim3(HID_/128, N_/128, R_*K_), 256, SM128>>>(
        prawA, (long long)K_*N_*2*V_, (long long)N_*2*V_, K_,
        pWrawT, (long long)K_*HID_*2*V_, (long long)HID_*2*V_, V_,
        I.b1, HID_,
        px1, CH_, (long long)N_*CH_, HID_, nullptr);

    // ---- rest of prolog ----
    k_u<<<1, 256>>>(I.eemb, I.w_extra);
    k_extra_pool<<<(R_ * N_) / 8, 256>>>(I.extra);
    k_splitB<<<dim3(VE_/32, HID_/32, 2), 256>>>(pWex, (long long)VE_*HID_, VE_, HID_,
                                                pWexT, (long long)HID_*2*VE_);
    k_splitB<<<dim3(OUT_/32, HID_/32, 2), 256>>>(pWlab, (long long)OUT_*HID_, OUT_, HID_,
                                                 pWlabT, (long long)HID_*2*OUT_);
    k_splitB<<<dim3(HID_/32, HID_/32, 5), 256>>>(I.W2, (long long)HID_*HID_, HID_, HID_,
                                                 pW2T, (long long)HID_*2*HID_);
    k_splitB<<<dim3(HID_/32, HID_/32, 1), 256>>>(I.Wf1, 0, HID_, HID_, pWf1T, 0);
    k_splitB<<<dim3(HID_/32, OUT_/32, 1), 256>>>(I.Wf2, 0, HID_, OUT_, pWf2T, 0);
    k_splitA<<<dim3(1024, 1, 2), 256>>>(I.label, (long long)N_*OUT_, OUT_, OUT_,
                                        plabA, (long long)N_*2*OUT_);
    k_splitA<<<dim3(2048, 1, 2), 256>>>(pxp, (long long)N_*VE_, VE_, VE_,
                                        pxpA, (long long)N_*2*VE_);

    // ---- x1 channels 3,4 for both r (z = r, zInner = 1) ----
    k_tc_gemm<128><<<dim3(HID_/128, N_/128, R_), 256, SM128>>>(
        pxpA, (long long)N_*2*VE_, 0, 1,
        pWexT, (long long)HID_*2*VE_, 0, VE_,
        I.b1 + 3*HID_, 0,
        px1 + 3*HID_, CH_, (long long)N_*CH_, 0, nullptr);
    k_tc_gemm<128><<<dim3(HID_/128, N_/128, R_), 256, SM128>>>(
        plabA, (long long)N_*2*OUT_, 0, 1,
        pWlabT, (long long)HID_*2*OUT_, 0, OUT_,
        I.b1 + 4*HID_, 0,
        px1 + 4*HID_, CH_, (long long)N_*CH_, 0, nullptr);

    // ---- LN1+split (both r), W2 GEMM (z=10), pool (both r) ----
    k_lnsplit<<<dim3(N_, R_), 256>>>(px1, I.g1, I.be1, I.a1, px1A);
    k_tc_gemm<128><<<dim3(HID_/128, N_/128, R_*C_), 256, SM128>>>(
        px1A, (long long)C_*N_*2*HID_, (long long)N_*2*HID_, C_,
        pW2T, 0, (long long)HID_*2*HID_, HID_,
        I.b2, HID_,
        px2, CH_, (long long)N_*CH_, HID_, nullptr);
    k_pool_c<<<dim3(N_, R_), 256>>>(I.g2, I.be2, I.a2, I.w_r);

    // ---- global pool + FFN head ----
    k_pool_global<<<N_ / 8, 256>>>(I.w_g);
    k_splitA<<<dim3(8192, 1, 1), 256>>>(phf, 0, HID_, HID_, phfA, 0);
    k_tc_gemm<128><<<dim3(HID_/128, N_/128, 1), 256, SM128>>>(
        phfA, 0, 0, 1, pWf1T, 0, 0, HID_,
        I.bf1, 0,
        px2, HID_, 0, 0, I.af);                        // PReLU out, [N,512]
    k_splitA<<<dim3(8192, 1, 1), 256>>>(px2, 0, HID_, HID_, pff1A, 0);
    k_tc_gemm<64><<<dim3(1, N_/128, 1), 128, SM64>>>(
        pff1A, 0, 0, 1, pWf2T, 0, 0, HID_,
        I.bf2, 0,
        (float*)d_out, OUT_, 0, 0, nullptr);
}

// round 16
// speedup vs baseline: 1.0464x; 1.0248x over previous
#include <cuda_runtime.h>
#include <cuda_bf16.h>
#include <math.h>

#define R_   2
#define K_   3
#define N_   16384
#define V_   256
#define L_   8
#define VE_  128
#define OUT_ 64
#define IN_  256
#define HID_ 512
#define C_   5
#define CH_  (C_*HID_)

// ---------------- fp32 workspace (both relations resident) ----------------
__device__ float g_x1[(size_t)R_ * N_ * CH_];
__device__ float g_x2[(size_t)R_ * N_ * CH_];
__device__ float g_outr[(size_t)R_ * N_ * HID_];
__device__ float g_u[R_ * VE_];
__device__ float g_Wraw[(size_t)R_ * K_ * V_ * HID_];
__device__ float g_Wex [(size_t)R_ * VE_ * HID_];
__device__ float g_Wlab[(size_t)R_ * OUT_ * HID_];

// ---------------- bf16 2-plane split workspace ([hi|lo], width 2K) ----------------
__device__ __align__(16) __nv_bfloat16 g_rawA[(size_t)R_ * K_ * N_ * (2*V_)];
__device__ __align__(16) __nv_bfloat16 g_labA[(size_t)R_ * N_ * (2*OUT_)];
__device__ __align__(16) __nv_bfloat16 g_xpA [(size_t)R_ * N_ * (2*VE_)];
__device__ __align__(16) __nv_bfloat16 g_x1A [(size_t)R_ * C_ * N_ * (2*HID_)];
__device__ __align__(16) __nv_bfloat16 g_hfA [(size_t)N_ * (2*HID_)];
__device__ __align__(16) __nv_bfloat16 g_ff1A[(size_t)N_ * (2*HID_)];
__device__ __align__(16) __nv_bfloat16 g_W2T  [(size_t)C_ * HID_ * (2*HID_)];
__device__ __align__(16) __nv_bfloat16 g_WrawT[(size_t)R_ * K_ * HID_ * (2*V_)];
__device__ __align__(16) __nv_bfloat16 g_WexT [(size_t)R_ * HID_ * (2*VE_)];
__device__ __align__(16) __nv_bfloat16 g_WlabT[(size_t)R_ * HID_ * (2*OUT_)];
__device__ __align__(16) __nv_bfloat16 g_Wf1T [(size_t)HID_ * (2*HID_)];
__device__ __align__(16) __nv_bfloat16 g_Wf2T [(size_t)OUT_ * (2*HID_)];

// ---------------- PTX helpers ----------------
__device__ __forceinline__ unsigned smem_u32(const void* p) {
    unsigned a;
    asm("{ .reg .u64 t; cvta.to.shared.u64 t, %1; cvt.u32.u64 %0, t; }" : "=r"(a) : "l"(p));
    return a;
}
__device__ __forceinline__ void cp16(unsigned dst, const void* src) {
    asm volatile("cp.async.cg.shared.global [%0], [%1], 16;" :: "r"(dst), "l"(src) : "memory");
}
__device__ __forceinline__ void ldsm4(unsigned* r, unsigned addr) {
    asm volatile("ldmatrix.sync.aligned.m8n8.x4.shared.b16 {%0,%1,%2,%3}, [%4];"
        : "=r"(r[0]), "=r"(r[1]), "=r"(r[2]), "=r"(r[3]) : "r"(addr));
}
__device__ __forceinline__ void mma16816(float* d, const unsigned* a, const unsigned* b) {
    asm volatile(
        "mma.sync.aligned.m16n8k16.row.col.f32.bf16.bf16.f32 "
        "{%0,%1,%2,%3}, {%4,%5,%6,%7}, {%8,%9}, {%0,%1,%2,%3};"
        : "+f"(d[0]), "+f"(d[1]), "+f"(d[2]), "+f"(d[3])
        : "r"(a[0]), "r"(a[1]), "r"(a[2]), "r"(a[3]), "r"(b[0]), "r"(b[1]));
}
// packed 64B-pitch smem layout with XOR swizzle (conflict-free STS.128 + ldsm)
__device__ __forceinline__ unsigned swz(int row, int c) {
    return (unsigned)((row << 6) + (((c ^ (row >> 1)) & 3) << 4) + ((c & ~3) << 4));
}
__device__ __forceinline__ void split2(float x, unsigned short& h, unsigned short& l) {
    __nv_bfloat16 hb = __float2bfloat16(x);
    __nv_bfloat16 lb = __float2bfloat16(x - __bfloat162float(hb));
    h = __bfloat16_as_ushort(hb); l = __bfloat16_as_ushort(lb);
}

// =========================================================================
// bf16 tensor-core GEMM, fused 3-product split per k-block.
// C = Ah.Bh^T + Ah.Bl^T + Al.Bh^T  (A,B 2-plane [hi|lo] along K).
// Packed swizzled smem -> 3 stages, 2 CTAs/SM. Round-13 fragment schedule.
// SPLIT epilogue mode writes bf16 2-plane [hi|lo] (row stride 2*tot) instead
// of fp32 — fuses the downstream splitA pass into the GEMM.
// =========================================================================
template<int BN, bool SPLIT>
__global__ void __launch_bounds__(128 * (BN > 64 ? BN / 64 : 1), 2) k_tc_gemm(
    const __nv_bfloat16* __restrict__ A, long long aZo, long long aZi, int zInner,
    const __nv_bfloat16* __restrict__ B, long long bZo, long long bZi, int Kd,
    const float* __restrict__ bias, long long biasZi,
    void* __restrict__ Co, int ldc, long long cZo, long long cZi,
    const float* __restrict__ alpha_p)
{
    constexpr int BM = 128, BK = 32;
    constexpr int NWN = (BN > 64 ? BN / 64 : 1);
    constexpr int THREADS = 128 * NWN;
    constexpr int WN  = BN / NWN;                 // 64
    constexpr int NT8 = WN / 8;                   // 8
    constexpr int ABP = BM * 64;
    constexpr int BBP = BN * 64;
    constexpr int STAGE = 2 * ABP + 2 * BBP;
    constexpr int APL = BM * 4, BPL = BN * 4;
    constexpr int TOT = 2 * (APL + BPL);

    extern __shared__ char smem[];
    const int tid = threadIdx.x, lane = tid & 31, wid = tid >> 5;
    const int warp_m = wid & 3, warp_n = wid >> 2;
    const int m0 = blockIdx.y * BM, n0 = blockIdx.x * BN;
    const int zo = blockIdx.z / zInner, zi = blockIdx.z % zInner;
    const int ldAB = 2 * Kd;
    const __nv_bfloat16* Az = A + (long long)zo * aZo + (long long)zi * aZi;
    const __nv_bfloat16* Bz = B + (long long)zo * bZo + (long long)zi * bZi;
    const float* biasz = bias ? bias + (long long)zi * biasZi : nullptr;

    const unsigned sb = smem_u32(smem);
    const int nkb = Kd / BK;

    float acc[2][NT8][4];
    #pragma unroll
    for (int mt = 0; mt < 2; mt++)
        #pragma unroll
        for (int nt = 0; nt < NT8; nt++)
            #pragma unroll
            for (int j = 0; j < 4; j++) acc[mt][nt][j] = 0.f;

    auto load = [&](int kb) {
        if (kb < nkb) {
            unsigned st = sb + (unsigned)(kb % 3) * STAGE;
            int k0 = kb * BK;
            #pragma unroll
            for (int q = 0; q < TOT / THREADS; q++) {
                int ch = tid + q * THREADS;
                unsigned dst; const __nv_bfloat16* src;
                if (ch < 2 * APL) {
                    int pl = (ch >= APL) ? 1 : 0;
                    int cc = ch - pl * APL;
                    int row = cc >> 2, c = cc & 3;
                    dst = st + pl * ABP + swz(row, c);
                    src = Az + (size_t)(m0 + row) * ldAB + pl * Kd + k0 + c * 8;
                } else {
                    int ch2 = ch - 2 * APL;
                    int pl = (ch2 >= BPL) ? 1 : 0;
                    int cc = ch2 - pl * BPL;
                    int row = cc >> 2, c = cc & 3;
                    dst = st + 2 * ABP + pl * BBP + swz(row, c);
                    src = Bz + (size_t)(n0 + row) * ldAB + pl * Kd + k0 + c * 8;
                }
                cp16(dst, src);
            }
        }
        asm volatile("cp.async.commit_group;" ::: "memory");
    };

    load(0); load(1);

    for (int kb = 0; kb < nkb; kb++) {
        asm volatile("cp.async.wait_group 1;" ::: "memory");
        __syncthreads();
        load(kb + 2);

        unsigned st = sb + (unsigned)(kb % 3) * STAGE;
        unsigned ah = st, al = st + ABP, bh = st + 2 * ABP, bl = bh + BBP;

        #pragma unroll
        for (int ks = 0; ks < 2; ks++) {
            unsigned af0[2][4], af1[2][4], bf[NT8 / 2][4];
            const int arow0 = warp_m * 32 + (lane & 15);
            const int c_a = 2 * ks + (lane >> 4);
            const unsigned aoff0 = swz(arow0, c_a);
            const unsigned aoff1 = swz(arow0 + 16, c_a);
            const int rowi = lane & 7, quad = lane >> 3;
            const int nofs = (quad >> 1) * 8;
            const int c_b = 2 * ks + (quad & 1);

            ldsm4(af0[0], ah + aoff0);
            ldsm4(af0[1], ah + aoff1);
            ldsm4(af1[0], al + aoff0);
            ldsm4(af1[1], al + aoff1);
            #pragma unroll
            for (int j = 0; j < NT8 / 2; j++) {
                int nb = warp_n * WN + j * 16 + nofs + rowi;
                ldsm4(bf[j], bh + swz(nb, c_b));
            }
            #pragma unroll
            for (int mt = 0; mt < 2; mt++)
                #pragma unroll
                for (int nt = 0; nt < NT8; nt++)
                    mma16816(acc[mt][nt], af0[mt], &bf[nt >> 1][(nt & 1) * 2]);
            #pragma unroll
            for (int j = 0; j < NT8 / 2; j++) {
                #pragma unroll
                for (int mt = 0; mt < 2; mt++) {
                    mma16816(acc[mt][2 * j + 0], af1[mt], &bf[j][0]);
                    mma16816(acc[mt][2 * j + 1], af1[mt], &bf[j][2]);
                }
                int nb = warp_n * WN + j * 16 + nofs + rowi;
                ldsm4(bf[j], bl + swz(nb, c_b));
            }
            #pragma unroll
            for (int mt = 0; mt < 2; mt++)
                #pragma unroll
                for (int nt = 0; nt < NT8; nt++)
                    mma16816(acc[mt][nt], af0[mt], &bf[nt >> 1][(nt & 1) * 2]);
        }
    }

    // ---- epilogue ----
    float alpha = alpha_p ? __ldg(alpha_p) : 0.f;
    int g = lane >> 2, q = lane & 3;
    #pragma unroll
    for (int mt = 0; mt < 2; mt++) {
        #pragma unroll
        for (int nt = 0; nt < NT8; nt++) {
            int col = n0 + warp_n * WN + nt * 8 + q * 2;
            float b0 = 0.f, b1 = 0.f;
            if (biasz) { b0 = biasz[col]; b1 = biasz[col + 1]; }
            #pragma unroll
            for (int half = 0; half < 2; half++) {
                int row = m0 + warp_m * 32 + mt * 16 + g + half * 8;
                float vx = acc[mt][nt][2 * half + 0] + b0;
                float vy = acc[mt][nt][2 * half + 1] + b1;
                if (alpha_p) {
                    vx = vx >= 0.f ? vx : alpha * vx;
                    vy = vy >= 0.f ? vy : alpha * vy;
                }
                if constexpr (SPLIT) {
                    // bf16 2-plane output: [row, 2*tot], hi at col, lo at tot+col
                    __nv_bfloat16* Cb = (__nv_bfloat16*)Co +
                        (long long)zo * cZo + (long long)zi * cZi;
                    int tot = gridDim.x * BN;
                    ushort2 h, l;
                    split2(vx, h.x, l.x); split2(vy, h.y, l.y);
                    *reinterpret_cast<ushort2*>(Cb + (size_t)row * 2 * tot + col) = h;
                    *reinterpret_cast<ushort2*>(Cb + (size_t)row * 2 * tot + tot + col) = l;
                } else {
                    float* Cf = (float*)Co + (long long)zo * cZo + (long long)zi * cZi;
                    *reinterpret_cast<float2*>(Cf + (size_t)row * ldc + col) =
                        make_float2(vx, vy);
                }
            }
        }
    }
}

// A-side split: fp32 [N_, ldin] -> bf16 [N_, 2K]
__global__ void __launch_bounds__(256) k_splitA(
    const float* __restrict__ in, long long inZ, int ldin, int K,
    __nv_bfloat16* __restrict__ out, long long outZ)
{
    long long z = blockIdx.z;
    in += z * inZ; out += z * outZ;
    int K4 = K / 4;
    int idx = blockIdx.x * 256 + threadIdx.x;
    if (idx >= N_ * K4) return;
    int m = idx / K4, k4 = (idx % K4) * 4;
    float4 v = *reinterpret_cast<const float4*>(in + (size_t)m * ldin + k4);
    ushort4 h, l;
    split2(v.x, h.x, l.x); split2(v.y, h.y, l.y);
    split2(v.z, h.z, l.z); split2(v.w, h.w, l.w);
    size_t b = (size_t)m * 2 * K;
    *reinterpret_cast<ushort4*>(out + b + k4) = h;
    *reinterpret_cast<ushort4*>(out + b + K + k4) = l;
}

// Fused per-row LN1 stats + LN + PReLU + split. Block per (n, r).
__global__ void __launch_bounds__(256) k_lnsplit(
    const float* __restrict__ x1,
    const float* __restrict__ g1, const float* __restrict__ be1,
    const float* __restrict__ a1p, __nv_bfloat16* __restrict__ out)
{
    int n = blockIdx.x, r = blockIdx.y, tid = threadIdx.x;
    __shared__ __align__(16) float sx[CH_];
    __shared__ float rsum[8], rsum2[8], smn, srs;
    const float* xr = x1 + ((size_t)r * N_ + n) * CH_;

    float s = 0.f, s2 = 0.f;
    for (int i = tid; i < CH_ / 4; i += 256) {
        float4 t = reinterpret_cast<const float4*>(xr)[i];
        reinterpret_cast<float4*>(sx)[i] = t;
        s  += t.x + t.y + t.z + t.w;
        s2 += t.x*t.x + t.y*t.y + t.z*t.z + t.w*t.w;
    }
    int lane = tid & 31, wid = tid >> 5;
    #pragma unroll
    for (int o = 16; o > 0; o >>= 1) {
        s  += __shfl_xor_sync(0xffffffffu, s,  o);
        s2 += __shfl_xor_sync(0xffffffffu, s2, o);
    }
    if (lane == 0) { rsum[wid] = s; rsum2[wid] = s2; }
    __syncthreads();
    if (tid == 0) {
        float ts = 0.f, ts2 = 0.f;
        #pragma unroll
        for (int w2 = 0; w2 < 8; w2++) { ts += rsum[w2]; ts2 += rsum2[w2]; }
        float m = ts / (float)CH_;
        smn = m; srs = rsqrtf(ts2 / (float)CH_ - m * m + 1e-5f);
    }
    __syncthreads();

    float mn = smn, rs = srs, a = __ldg(a1p);
    for (int i4 = tid; i4 < CH_ / 4; i4 += 256) {
        int i = i4 * 4;
        int c = i / HID_, col = i % HID_;
        float4 v = reinterpret_cast<const float4*>(sx)[i4];
        float4 g = reinterpret_cast<const float4*>(g1)[i4];
        float4 b = reinterpret_cast<const float4*>(be1)[i4];
        v.x = (v.x-mn)*rs*g.x + b.x; v.y = (v.y-mn)*rs*g.y + b.y;
        v.z = (v.z-mn)*rs*g.z + b.z; v.w = (v.w-mn)*rs*g.w + b.w;
        v.x = v.x >= 0.f ? v.x : a*v.x; v.y = v.y >= 0.f ? v.y : a*v.y;
        v.z = v.z >= 0.f ? v.z : a*v.z; v.w = v.w >= 0.f ? v.w : a*v.w;
        ushort4 h, l;
        split2(v.x, h.x, l.x); split2(v.y, h.y, l.y);
        split2(v.z, h.z, l.z); split2(v.w, h.w, l.w);
        __nv_bfloat16* op = out + ((size_t)r * C_ + c) * N_ * (2*HID_) + (size_t)n * (2*HID_);
        *reinterpret_cast<ushort4*>(op + col) = h;
        *reinterpret_cast<ushort4*>(op + HID_ + col) = l;
    }
}

// B-side split: fp32 [Kd, Nn] -> bf16 [Nn, 2Kd], coalesced via smem transpose
__global__ void __launch_bounds__(256) k_splitB(
    const float* __restrict__ in, long long inZ, int Kd, int Nn,
    __nv_bfloat16* __restrict__ out, long long outZ)
{
    __shared__ float tile[32][33];
    long long z = blockIdx.z;
    in += z * inZ; out += z * outZ;
    int k0 = blockIdx.x * 32, n0 = blockIdx.y * 32;
    int tx = threadIdx.x & 31, ty = threadIdx.x >> 5;
    #pragma unroll
    for (int j = 0; j < 32; j += 8)
        tile[ty + j][tx] = in[(size_t)(k0 + ty + j) * Nn + n0 + tx];
    __syncthreads();
    #pragma unroll
    for (int j = 0; j < 32; j += 8) {
        int n = n0 + ty + j, k = k0 + tx;
        float x = tile[tx][ty + j];
        unsigned short h, l;
        split2(x, h, l);
        size_t b = (size_t)n * 2 * Kd;
        out[b + k] = __ushort_as_bfloat16(h);
        out[b + Kd + k] = __ushort_as_bfloat16(l);
    }
}

// ---------------- plain fp32 GEMM for tiny weight fusion ----------------
__global__ void __launch_bounds__(256, 2) fuse_weights_kernel(
    const float* __restrict__ femb, const float* __restrict__ eemb,
    const float* __restrict__ lemb, const float* __restrict__ W1)
{
    constexpr int BM = 64, TM = 4, BN = 128, BK = 16, TN = 8;
    int zz = blockIdx.z, r = zz / C_, c = zz % C_;
    const float* A; int M; float* out;
    if (c < K_)      { A = femb + (size_t)(r*K_+c)*V_*IN_; M = V_;   out = g_Wraw + (size_t)(r*K_+c)*V_*HID_; }
    else if (c == 3) { A = eemb + (size_t)r*VE_*IN_;       M = VE_;  out = g_Wex  + (size_t)r*VE_*HID_; }
    else             { A = lemb + (size_t)r*OUT_*IN_;      M = OUT_; out = g_Wlab + (size_t)r*OUT_*HID_; }
    const float* B = W1 + (size_t)c * IN_ * HID_;

    __shared__ __align__(16) float As[BK][BM+4];
    __shared__ __align__(16) float Bs[BK][BN];
    int tid = threadIdx.x, tx = tid % (BN/TN), ty = tid / (BN/TN);
    int row0 = blockIdx.y * BM, col0 = blockIdx.x * BN;
    float acc[TM][TN] = {};
    for (int k0 = 0; k0 < IN_; k0 += BK) {
        for (int v = tid; v < BM*(BK/4); v += 256) {
            int rr = v / (BK/4), kq = (v % (BK/4)) * 4, gr = row0 + rr;
            float4 val = make_float4(0,0,0,0);
            if (gr < M) val = *reinterpret_cast<const float4*>(A + (size_t)gr*IN_ + k0 + kq);
            As[kq][rr] = val.x; As[kq+1][rr] = val.y; As[kq+2][rr] = val.z; As[kq+3][rr] = val.w;
        }
        for (int v = tid; v < BK*(BN/4); v += 256) {
            int rr = v / (BN/4), c4 = (v % (BN/4)) * 4;
            *reinterpret_cast<float4*>(&Bs[rr][c4]) =
                *reinterpret_cast<const float4*>(B + (size_t)(k0+rr)*HID_ + col0 + c4);
        }
        __syncthreads();
        #pragma unroll
        for (int kk = 0; kk < BK; kk++) {
            float a[TM], b[TN];
            #pragma unroll
            for (int i = 0; i < TM; i++) a[i] = As[kk][ty*TM+i];
            #pragma unroll
            for (int j = 0; j < TN; j++) b[j] = Bs[kk][tx*TN+j];
            #pragma unroll
            for (int i = 0; i < TM; i++)
                #pragma unroll
                for (int j = 0; j < TN; j++) acc[i][j] += a[i]*b[j];
        }
        __syncthreads();
    }
    #pragma unroll
    for (int i = 0; i < TM; i++) {
        int gr = row0 + ty*TM + i;
        if (gr >= M) continue;
        #pragma unroll
        for (int j = 0; j < TN; j++) out[(size_t)gr*HID_ + col0 + tx*TN + j] = acc[i][j];
    }
}

// ---------------- small SIMT kernels ----------------
__global__ void k_u(const float* __restrict__ eemb, const float* __restrict__ wx)
{
    int t = blockIdx.x * blockDim.x + threadIdx.x;
    if (t >= R_ * VE_) return;
    const float* row = eemb + (size_t)t * IN_;
    float s = 0.f;
    for (int d = 0; d < IN_; d++) s += row[d] * wx[d];
    g_u[t] = s;
}

// extra-feature attention pool; writes bf16 2-plane split DIRECTLY to g_xpA
__global__ void __launch_bounds__(256) k_extra_pool(const float* __restrict__ extra)
{
    int wg = (blockIdx.x * blockDim.x + threadIdx.x) >> 5, lane = threadIdx.x & 31;
    if (wg >= R_ * N_) return;
    int r = wg / N_;
    const float* base = extra + (size_t)wg * (L_ * VE_);
    float u[4];
    #pragma unroll
    for (int j = 0; j < 4; j++) u[j] = g_u[r * VE_ + lane + 32*j];
    float x[L_][4], s[L_];
    #pragma unroll
    for (int l = 0; l < L_; l++) {
        float p = 0.f;
        #pragma unroll
        for (int j = 0; j < 4; j++) { x[l][j] = base[l*VE_ + lane + 32*j]; p += x[l][j]*u[j]; }
        #pragma unroll
        for (int o = 16; o > 0; o >>= 1) p += __shfl_xor_sync(0xffffffffu, p, o);
        s[l] = 1.f / (1.f + expf(-p));
    }
    float mx = s[0];
    #pragma unroll
    for (int l = 1; l < L_; l++) mx = fmaxf(mx, s[l]);
    float e[L_], es = 0.f;
    #pragma unroll
    for (int l = 0; l < L_; l++) { e[l] = expf(s[l]-mx); es += e[l]; }
    float inv = 1.f / es, out[4] = {0,0,0,0};
    #pragma unroll
    for (int l = 0; l < L_; l++) {
        float w = e[l]*inv;
        #pragma unroll
        for (int j = 0; j < 4; j++) out[j] += w * x[l][j];
    }
    __nv_bfloat16* op = g_xpA + (size_t)wg * (2 * VE_);
    #pragma unroll
    for (int j = 0; j < 4; j++) {
        unsigned short h, l2;
        split2(out[j], h, l2);
        op[lane + 32*j] = __ushort_as_bfloat16(h);
        op[VE_ + lane + 32*j] = __ushort_as_bfloat16(l2);
    }
}

// channel attention pool with in-block LN2; block per (n, r)
__global__ void __launch_bounds__(256) k_pool_c(
    const float* __restrict__ g2, const float* __restrict__ be2,
    const float* __restrict__ a2p, const float* __restrict__ w_r)
{
    int n = blockIdx.x, r = blockIdx.y, tid = threadIdx.x;
    __shared__ __align__(16) float sx[CH_];
    __shared__ float red[C_][8], rsum[8], rsum2[8], salpha[C_], smn, srs;
    const float* xr = g_x2 + ((size_t)r * N_ + n) * CH_;
    const float* wr = w_r + r * HID_;
    float s = 0.f, s2 = 0.f;
    for (int i = tid; i < CH_/4; i += 256) {
        float4 t = reinterpret_cast<const float4*>(xr)[i];
        reinterpret_cast<float4*>(sx)[i] = t;
        s += t.x+t.y+t.z+t.w; s2 += t.x*t.x+t.y*t.y+t.z*t.z+t.w*t.w;
    }
    int lane = tid & 31, wid = tid >> 5;
    #pragma unroll
    for (int o = 16; o > 0; o >>= 1) {
        s += __shfl_xor_sync(0xffffffffu, s, o);
        s2 += __shfl_xor_sync(0xffffffffu, s2, o);
    }
    if (lane == 0) { rsum[wid] = s; rsum2[wid] = s2; }
    __syncthreads();
    if (tid == 0) {
        float ts = 0.f, ts2 = 0.f;
        #pragma unroll
        for (int w2 = 0; w2 < 8; w2++) { ts += rsum[w2]; ts2 += rsum2[w2]; }
        float m = ts/(float)CH_;
        smn = m; srs = rsqrtf(ts2/(float)CH_ - m*m + 1e-5f);
    }
    __syncthreads();
    float mn = smn, rs = srs, a = __ldg(a2p);
    for (int i = tid; i < CH_; i += 256) {
        float v = (sx[i]-mn)*rs*g2[i] + be2[i];
        sx[i] = v >= 0.f ? v : a*v;
    }
    __syncthreads();
    float p[C_] = {0,0,0,0,0};
    for (int h = tid; h < HID_; h += 256) {
        float w = wr[h];
        #pragma unroll
        for (int c = 0; c < C_; c++) p[c] += sx[c*HID_+h] * w;
    }
    #pragma unroll
    for (int c = 0; c < C_; c++)
        #pragma unroll
        for (int o = 16; o > 0; o >>= 1) p[c] += __shfl_xor_sync(0xffffffffu, p[c], o);
    if (lane == 0)
        #pragma unroll
        for (int c = 0; c < C_; c++) red[c][wid] = p[c];
    __syncthreads();
    if (tid == 0) {
        float sv[C_], mx = -1e30f;
        #pragma unroll
        for (int c = 0; c < C_; c++) {
            float t = 0.f;
            #pragma unroll
            for (int w2 = 0; w2 < 8; w2++) t += red[c][w2];
            sv[c] = 1.f / (1.f + expf(-t)); mx = fmaxf(mx, sv[c]);
        }
        float es = 0.f, e[C_];
        #pragma unroll
        for (int c = 0; c < C_; c++) { e[c] = expf(sv[c]-mx); es += e[c]; }
        #pragma unroll
        for (int c = 0; c < C_; c++) salpha[c] = e[c] / es;
    }
    __syncthreads();
    float* op = g_outr + ((size_t)r * N_ + n) * HID_;
    for (int h = tid; h < HID_; h += 256) {
        float acc = 0.f;
        #pragma unroll
        for (int c = 0; c < C_; c++) acc += salpha[c] * sx[c*HID_+h];
        op[h] = acc;
    }
}

// global (over R) attention pool; writes bf16 2-plane split DIRECTLY to g_hfA
__global__ void __launch_bounds__(256) k_pool_global(const float* __restrict__ wg)
{
    int w = (blockIdx.x * blockDim.x + threadIdx.x) >> 5, lane = threadIdx.x & 31;
    if (w >= N_) return;
    const float* pa = g_outr + (size_t)w * HID_;
    const float* pb = g_outr + (size_t)N_ * HID_ + (size_t)w * HID_;
    float a[16], b[16], sa = 0.f, sb = 0.f;
    #pragma unroll
    for (int j = 0; j < 16; j++) {
        int h = lane + 32*j;
        a[j] = pa[h]; b[j] = pb[h];
        float wv = wg[h];
        sa += a[j]*wv; sb += b[j]*wv;
    }
    #pragma unroll
    for (int o = 16; o > 0; o >>= 1) {
        sa += __shfl_xor_sync(0xffffffffu, sa, o);
        sb += __shfl_xor_sync(0xffffffffu, sb, o);
    }
    sa = 1.f/(1.f+expf(-sa)); sb = 1.f/(1.f+expf(-sb));
    float mx = fmaxf(sa, sb), ea = expf(sa-mx), eb = expf(sb-mx);
    float aa = ea/(ea+eb), ab = 1.f - aa;
    __nv_bfloat16* op = g_hfA + (size_t)w * (2 * HID_);
    #pragma unroll
    for (int j = 0; j < 16; j++) {
        int h = lane + 32*j;
        unsigned short hh, ll;
        split2(aa*a[j] + ab*b[j], hh, ll);
        op[h] = __ushort_as_bfloat16(hh);
        op[HID_ + h] = __ushort_as_bfloat16(ll);
    }
}

// ---------------- input mapping ----------------
struct Ins {
    const float *raw, *extra, *label, *femb, *eemb, *lemb;
    const float *w_extra, *w_r, *w_g;
    const float *W1, *b1, *g1, *be1, *a1, *W2, *b2, *g2, *be2, *a2;
    const float *Wf1, *bf1, *af, *Wf2, *bf2;
};
static void resolve(void* const* d_in, const int* sz, Ins& I)
{
    auto F = [&](int i) { return (const float*)d_in[i]; };
    if (sz[0] == R_ * K_ * N_ * V_) {
        I.raw=F(0); I.extra=F(1); I.label=F(2); I.femb=F(3); I.eemb=F(4); I.lemb=F(5);
        I.w_extra=F(6); I.w_r=F(7); I.w_g=F(8);
        I.W1=F(9); I.b1=F(10); I.g1=F(11); I.be1=F(12); I.a1=F(13);
        I.W2=F(14); I.b2=F(15); I.g2=F(16); I.be2=F(17); I.a2=F(18);
        I.Wf1=F(19); I.bf1=F(20); I.af=F(21); I.Wf2=F(22); I.bf2=F(23);
    } else {
        I.W1=F(0); I.W2=F(1); I.Wf1=F(2); I.Wf2=F(3);
        I.a1=F(4); I.a2=F(5); I.af=F(6);
        I.b1=F(7); I.b2=F(8); I.be1=F(9); I.be2=F(10); I.bf1=F(11); I.bf2=F(12);
        I.eemb=F(13); I.extra=F(14); I.femb=F(15); I.g1=F(16); I.g2=F(17);
        I.lemb=F(18); I.label=F(19); I.raw=F(20);
        I.w_extra=F(21); I.w_g=F(22); I.w_r=F(23);
    }
}

extern "C" void kernel_launch(void* const* d_in, const int* in_sizes, int n_in,
                              void* d_out, int out_size)
{
    if (n_in < 24) return;
    Ins I; resolve(d_in, in_sizes, I);

    float *px1, *px2, *pWraw, *pWex, *pWlab;
    __nv_bfloat16 *prawA, *plabA, *pxpA, *px1A, *phfA, *pff1A;
    __nv_bfloat16 *pW2T, *pWrawT, *pWexT, *pWlabT, *pWf1T, *pWf2T;
    cudaGetSymbolAddress((void**)&px1, g_x1);     cudaGetSymbolAddress((void**)&px2, g_x2);
    cudaGetSymbolAddress((void**)&pWraw, g_Wraw);
    cudaGetSymbolAddress((void**)&pWex, g_Wex);   cudaGetSymbolAddress((void**)&pWlab, g_Wlab);
    cudaGetSymbolAddress((void**)&prawA, g_rawA); cudaGetSymbolAddress((void**)&plabA, g_labA);
    cudaGetSymbolAddress((void**)&pxpA, g_xpA);   cudaGetSymbolAddress((void**)&px1A, g_x1A);
    cudaGetSymbolAddress((void**)&phfA, g_hfA);   cudaGetSymbolAddress((void**)&pff1A, g_ff1A);
    cudaGetSymbolAddress((void**)&pW2T, g_W2T);   cudaGetSymbolAddress((void**)&pWrawT, g_WrawT);
    cudaGetSymbolAddress((void**)&pWexT, g_WexT); cudaGetSymbolAddress((void**)&pWlabT, g_WlabT);
    cudaGetSymbolAddress((void**)&pWf1T, g_Wf1T); cudaGetSymbolAddress((void**)&pWf2T, g_Wf2T);

    constexpr int SM128 = 3 * (2 * 128 * 64 + 2 * 128 * 64);   // 98304 B -> 2 CTAs/SM
    constexpr int SM64  = 3 * (2 * 128 * 64 + 2 * 64 * 64);    // 73728 B
    cudaFuncSetAttribute(k_tc_gemm<128, false>, cudaFuncAttributeMaxDynamicSharedMemorySize, SM128);
    cudaFuncSetAttribute(k_tc_gemm<128, true>,  cudaFuncAttributeMaxDynamicSharedMemorySize, SM128);
    cudaFuncSetAttribute(k_tc_gemm<64, false>,  cudaFuncAttributeMaxDynamicSharedMemorySize, SM64);

    // ---- launches ordered so #4 = raw GEMM (ncu capture position) ----
    fuse_weights_kernel<<<dim3(4, 4, 10), 256>>>(I.femb, I.eemb, I.lemb, I.W1);            // 1
    k_splitB<<<dim3(V_/32, HID_/32, 6), 256>>>(pWraw, (long long)V_*HID_, V_, HID_,
                                               pWrawT, (long long)HID_*2*V_);              // 2
    k_splitA<<<dim3(4096, 1, 6), 256>>>(I.raw, (long long)N_*V_, V_, V_,
                                        prawA, (long long)N_*2*V_);                        // 3
    k_tc_gemm<128, false><<<dim3(HID_/128, N_/128, R_*K_), 256, SM128>>>(
        prawA, (long long)K_*N_*2*V_, (long long)N_*2*V_, K_,
        pWrawT, (long long)K_*HID_*2*V_, (long long)HID_*2*V_, V_,
        I.b1, HID_,
        px1, CH_, (long long)N_*CH_, HID_, nullptr);                                       // 4

    // ---- rest of prolog ----
    k_u<<<1, 256>>>(I.eemb, I.w_extra);
    k_extra_pool<<<(R_ * N_) / 8, 256>>>(I.extra);   // writes xpA split directly
    k_splitB<<<dim3(VE_/32, HID_/32, 2), 256>>>(pWex, (long long)VE_*HID_, VE_, HID_,
                                                pWexT, (long long)HID_*2*VE_);
    k_splitB<<<dim3(OUT_/32, HID_/32, 2), 256>>>(pWlab, (long long)OUT_*HID_, OUT_, HID_,
                                                 pWlabT, (long long)HID_*2*OUT_);
    k_splitB<<<dim3(HID_/32, HID_/32, 5), 256>>>(I.W2, (long long)HID_*HID_, HID_, HID_,
                                                 pW2T, (long long)HID_*2*HID_);
    k_splitB<<<dim3(HID_/32, HID_/32, 1), 256>>>(I.Wf1, 0, HID_, HID_, pWf1T, 0);
    k_splitB<<<dim3(HID_/32, OUT_/32, 1), 256>>>(I.Wf2, 0, HID_, OUT_, pWf2T, 0);
    k_splitA<<<dim3(1024, 1, 2), 256>>>(I.label, (long long)N_*OUT_, OUT_, OUT_,
                                        plabA, (long long)N_*2*OUT_);

    // ---- x1 channels 3,4 for both r (z = r, zInner = 1) ----
    k_tc_gemm<128, false><<<dim3(HID_/128, N_/128, R_), 256, SM128>>>(
        pxpA, (long long)N_*2*VE_, 0, 1,
        pWexT, (long long)HID_*2*VE_, 0, VE_,
        I.b1 + 3*HID_, 0,
        px1 + 3*HID_, CH_, (long long)N_*CH_, 0, nullptr);
    k_tc_gemm<128, false><<<dim3(HID_/128, N_/128, R_), 256, SM128>>>(
        plabA, (long long)N_*2*OUT_, 0, 1,
        pWlabT, (long long)HID_*2*OUT_, 0, OUT_,
        I.b1 + 4*HID_, 0,
        px1 + 4*HID_, CH_, (long long)N_*CH_, 0, nullptr);

    // ---- LN1+split (both r), W2 GEMM (z=10), pool (both r) ----
    k_lnsplit<<<dim3(N_, R_), 256>>>(px1, I.g1, I.be1, I.a1, px1A);
    k_tc_gemm<128, false><<<dim3(HID_/128, N_/128, R_*C_), 256, SM128>>>(
        px1A, (long long)C_*N_*2*HID_, (long long)N_*2*HID_, C_,
        pW2T, 0, (long long)HID_*2*HID_, HID_,
        I.b2, HID_,
        px2, CH_, (long long)N_*CH_, HID_, nullptr);
    k_pool_c<<<dim3(N_, R_), 256>>>(I.g2, I.be2, I.a2, I.w_r);

    // ---- global pool (split out) + FFN head (split epilogue) ----
    k_pool_global<<<N_ / 8, 256>>>(I.w_g);           // writes hfA split directly
    k_tc_gemm<128, true><<<dim3(HID_/128, N_/128, 1), 256, SM128>>>(
        phfA, 0, 0, 1, pWf1T, 0, 0, HID_,
        I.bf1, 0,
        pff1A, 0, 0, 0, I.af);                       // PReLU + split out -> ff1A
    k_tc_gemm<64, false><<<dim3(1, N_/128, 1), 128, SM64>>>(
        pff1A, 0, 0, 1, pWf2T, 0, 0, HID_,
        I.bf2, 0,
        d_out, OUT_, 0, 0, nullptr);
}